// round 1
// baseline (speedup 1.0000x reference)
#include <cuda_runtime.h>
#include <math.h>

// Problem constants
#define IDIM   384
#define JDIM   384
#define NTOK   (IDIM*JDIM)      // 147456
#define CDIM   128
#define HEADS  4
#define HDIM   32
#define QSCALE 0.17677669529663687f   // 1/sqrt(32)

// -------- scratch (device globals; no allocation allowed) --------
__device__ float g_xln[(size_t)NTOK*CDIM];
__device__ float g_q  [(size_t)NTOK*CDIM];
__device__ float g_k  [(size_t)NTOK*CDIM];
__device__ float g_v  [(size_t)NTOK*CDIM];
__device__ float g_gt [(size_t)NTOK*CDIM];
__device__ float g_og [(size_t)NTOK*CDIM];
__device__ float g_tb [(size_t)HEADS*NTOK];   // [h][q*384 + k]

// =====================================================================
// Kernel 1: LayerNorm + tri-bias projection (x @ wz + bz)
// one warp per token (C=128 -> 4 floats per lane)
// =====================================================================
__global__ __launch_bounds__(256) void ln_z_kernel(
    const float* __restrict__ x,
    const float* __restrict__ lnw, const float* __restrict__ lnb,
    const float* __restrict__ wz,  const float* __restrict__ bz)
{
    int warp = threadIdx.x >> 5;
    int lane = threadIdx.x & 31;
    size_t token = (size_t)blockIdx.x * 8 + warp;

    float4 xv = ((const float4*)(x + token * CDIM))[lane];

    float s = xv.x + xv.y + xv.z + xv.w;
#pragma unroll
    for (int m = 16; m; m >>= 1) s += __shfl_xor_sync(0xffffffffu, s, m);
    float mu = s * (1.0f / 128.0f);

    float dx = xv.x - mu, dy = xv.y - mu, dz = xv.z - mu, dw = xv.w - mu;
    float s2 = dx*dx + dy*dy + dz*dz + dw*dw;
#pragma unroll
    for (int m = 16; m; m >>= 1) s2 += __shfl_xor_sync(0xffffffffu, s2, m);
    float rstd = rsqrtf(s2 * (1.0f / 128.0f) + 1e-5f);

    float4 wv = ((const float4*)lnw)[lane];
    float4 bv = ((const float4*)lnb)[lane];
    float4 y;
    y.x = dx * rstd * wv.x + bv.x;
    y.y = dy * rstd * wv.y + bv.y;
    y.z = dz * rstd * wv.z + bv.z;
    y.w = dw * rstd * wv.w + bv.w;
    ((float4*)(g_xln + token * CDIM))[lane] = y;

    // tri-bias: z[h] = sum_c y[c] * wz[c][h]   (wz row-major [128][4])
    const float4* wzr = (const float4*)wz;     // each row = 4 head weights
    int c = lane * 4;
    float4 w0 = wzr[c], w1 = wzr[c+1], w2 = wzr[c+2], w3 = wzr[c+3];
    float4 a;
    a.x = y.x*w0.x + y.y*w1.x + y.z*w2.x + y.w*w3.x;
    a.y = y.x*w0.y + y.y*w1.y + y.z*w2.y + y.w*w3.y;
    a.z = y.x*w0.z + y.y*w1.z + y.z*w2.z + y.w*w3.z;
    a.w = y.x*w0.w + y.y*w1.w + y.z*w2.w + y.w*w3.w;
#pragma unroll
    for (int m = 16; m; m >>= 1) {
        a.x += __shfl_xor_sync(0xffffffffu, a.x, m);
        a.y += __shfl_xor_sync(0xffffffffu, a.y, m);
        a.z += __shfl_xor_sync(0xffffffffu, a.z, m);
        a.w += __shfl_xor_sync(0xffffffffu, a.w, m);
    }
    if (lane == 0) {
        g_tb[0*(size_t)NTOK + token] = a.x + bz[0];
        g_tb[1*(size_t)NTOK + token] = a.y + bz[1];
        g_tb[2*(size_t)NTOK + token] = a.z + bz[2];
        g_tb[3*(size_t)NTOK + token] = a.w + bz[3];
    }
}

// =====================================================================
// Kernel 2: generic [128-row tile] x [128x128 weight] GEMM
// modes: 0 = *QSCALE (q) ; 1 = plain (k, v) ; 3 = sigmoid(.+bias) (gate)
//        4 = +bias (output projection)
// =====================================================================
#define GEMM_AS_STRIDE 132
#define GEMM_SMEM_BYTES ((128*GEMM_AS_STRIDE + 128*128)*4)

__global__ __launch_bounds__(256) void gemm128(
    const float* __restrict__ A, const float* __restrict__ W,
    float* __restrict__ out, const float* __restrict__ bias, int mode)
{
    extern __shared__ float sm[];
    float* As = sm;                       // [128][132]
    float* Bs = sm + 128 * GEMM_AS_STRIDE;  // [128][128]

    int tid = threadIdx.x;
    size_t rowbase = (size_t)blockIdx.x * 128;

    // load A tile (row-major, float4, conflict-free)
#pragma unroll
    for (int it = 0; it < 16; it++) {
        int idx = tid + it * 256;
        int m  = idx >> 5;
        int k4 = (idx & 31) << 2;
        *(float4*)(As + m * GEMM_AS_STRIDE + k4) =
            *(const float4*)(A + (rowbase + m) * CDIM + k4);
    }
    // load W tile
#pragma unroll
    for (int it = 0; it < 16; it++) {
        int idx = tid + it * 256;
        int k  = idx >> 5;
        int n4 = (idx & 31) << 2;
        *(float4*)(Bs + k * 128 + n4) = *(const float4*)(W + k * 128 + n4);
    }
    __syncthreads();

    int tm = (tid >> 4) << 3;   // 0..120
    int tn = (tid & 15) << 3;   // 0..120

    float acc[8][8];
#pragma unroll
    for (int i = 0; i < 8; i++)
#pragma unroll
        for (int j = 0; j < 8; j++) acc[i][j] = 0.0f;

    for (int k4 = 0; k4 < 128; k4 += 4) {
        float4 am[8];
#pragma unroll
        for (int i = 0; i < 8; i++)
            am[i] = *(float4*)(As + (tm + i) * GEMM_AS_STRIDE + k4);
#pragma unroll
        for (int kk = 0; kk < 4; kk++) {
            float4 b0 = *(float4*)(Bs + (k4 + kk) * 128 + tn);
            float4 b1 = *(float4*)(Bs + (k4 + kk) * 128 + tn + 4);
            float bv[8] = {b0.x, b0.y, b0.z, b0.w, b1.x, b1.y, b1.z, b1.w};
#pragma unroll
            for (int i = 0; i < 8; i++) {
                float a = (kk == 0) ? am[i].x : (kk == 1) ? am[i].y
                        : (kk == 2) ? am[i].z : am[i].w;
#pragma unroll
                for (int j = 0; j < 8; j++) acc[i][j] += a * bv[j];
            }
        }
    }

    // epilogue
    float bb[8];
    if (mode == 3 || mode == 4) {
#pragma unroll
        for (int j = 0; j < 8; j++) bb[j] = bias[tn + j];
    }
#pragma unroll
    for (int i = 0; i < 8; i++) {
        float v[8];
#pragma unroll
        for (int j = 0; j < 8; j++) {
            float t = acc[i][j];
            if (mode == 0) t *= QSCALE;
            else if (mode == 3) t = 1.0f / (1.0f + __expf(-(t + bb[j])));
            else if (mode == 4) t += bb[j];
            v[j] = t;
        }
        float* orow = out + (rowbase + tm + i) * CDIM + tn;
        *(float4*)(orow)     = make_float4(v[0], v[1], v[2], v[3]);
        *(float4*)(orow + 4) = make_float4(v[4], v[5], v[6], v[7]);
    }
}

// =====================================================================
// Kernel 3: attention per (q-tile=32, head, i-row)
//   S = Q Kt (q pre-scaled) + tri_bias[h,q,k] + 1e9*(mask[i,k]-1)
//   softmax over k, O = P V, gate multiply fused, write g_og
// =====================================================================
#define KS_STRIDE 36
#define S_STRIDE  388
#define ATTN_SMEM_FLOATS (32*KS_STRIDE + 2*384*KS_STRIDE + 32*S_STRIDE + 384)
#define ATTN_SMEM_BYTES  (ATTN_SMEM_FLOATS*4)

__global__ __launch_bounds__(256) void attn_kernel(const float* __restrict__ mask)
{
    extern __shared__ float sm[];
    float* Qs = sm;                       // [32][36]
    float* Ks = Qs + 32 * KS_STRIDE;      // [384][36]
    float* Vs = Ks + 384 * KS_STRIDE;     // [384][36]
    float* S  = Vs + 384 * KS_STRIDE;     // [32][388]
    float* Ms = S  + 32 * S_STRIDE;       // [384]

    int tid = threadIdx.x;
    int qt  = blockIdx.x;                 // 0..11
    int h   = blockIdx.y;                 // 0..3
    int i   = blockIdx.z;                 // 0..383
    size_t base = (size_t)i * JDIM;
    int col0 = h * HDIM;
    int qbase = qt * 32;

    // load Q tile
    {
        int q  = tid >> 3;
        int d4 = (tid & 7) << 2;
        *(float4*)(Qs + q * KS_STRIDE + d4) =
            *(const float4*)(g_q + (base + qbase + q) * CDIM + col0 + d4);
    }
    // load K, V
#pragma unroll
    for (int it = 0; it < 12; it++) {
        int idx = tid + it * 256;
        int k  = idx >> 3;
        int d4 = (idx & 7) << 2;
        *(float4*)(Ks + k * KS_STRIDE + d4) =
            *(const float4*)(g_k + (base + k) * CDIM + col0 + d4);
        *(float4*)(Vs + k * KS_STRIDE + d4) =
            *(const float4*)(g_v + (base + k) * CDIM + col0 + d4);
    }
    // mask bias
    for (int k = tid; k < 384; k += 256)
        Ms[k] = 1e9f * (mask[base + k] - 1.0f);
    __syncthreads();

    // ---- S = Q Kt : 4q x 12k register tile per thread ----
    int qg = tid >> 5;   // 0..7
    int kg = tid & 31;   // 0..31
    float acc[4][12];
#pragma unroll
    for (int a = 0; a < 4; a++)
#pragma unroll
        for (int b = 0; b < 12; b++) acc[a][b] = 0.0f;

#pragma unroll
    for (int d4 = 0; d4 < 32; d4 += 4) {
        float4 qf[4];
#pragma unroll
        for (int iq = 0; iq < 4; iq++)
            qf[iq] = *(float4*)(Qs + (qg + 8 * iq) * KS_STRIDE + d4);
#pragma unroll
        for (int ik = 0; ik < 12; ik++) {
            float4 kf = *(float4*)(Ks + (kg + 32 * ik) * KS_STRIDE + d4);
#pragma unroll
            for (int iq = 0; iq < 4; iq++)
                acc[iq][ik] += qf[iq].x*kf.x + qf[iq].y*kf.y
                             + qf[iq].z*kf.z + qf[iq].w*kf.w;
        }
    }
    const float* tbh = g_tb + (size_t)h * NTOK;
#pragma unroll
    for (int iq = 0; iq < 4; iq++) {
        int q = qg + 8 * iq;
        const float* tbrow = tbh + (size_t)(qbase + q) * JDIM;
#pragma unroll
        for (int ik = 0; ik < 12; ik++) {
            int k = kg + 32 * ik;
            S[q * S_STRIDE + k] = acc[iq][ik] + tbrow[k] + Ms[k];
        }
    }
    __syncthreads();

    // ---- softmax over k (8 threads per row) ----
    {
        int row = tid >> 3;
        int sub = tid & 7;
        float* srow = S + row * S_STRIDE;
        float mx = -1e30f;
#pragma unroll
        for (int t = 0; t < 48; t++) mx = fmaxf(mx, srow[sub + 8 * t]);
#pragma unroll
        for (int m = 4; m; m >>= 1)
            mx = fmaxf(mx, __shfl_xor_sync(0xffffffffu, mx, m));
        float sum = 0.0f;
#pragma unroll
        for (int t = 0; t < 48; t++) {
            float e = __expf(srow[sub + 8 * t] - mx);
            srow[sub + 8 * t] = e;
            sum += e;
        }
#pragma unroll
        for (int m = 4; m; m >>= 1)
            sum += __shfl_xor_sync(0xffffffffu, sum, m);
        float inv = 1.0f / sum;
#pragma unroll
        for (int t = 0; t < 48; t++) srow[sub + 8 * t] *= inv;
    }
    __syncthreads();

    // ---- O = P V, fuse gate multiply, write g_og ----
    {
        int q  = tid >> 3;
        int dg = (tid & 7) << 2;
        const float* srow = S + q * S_STRIDE;
        float4 o = make_float4(0.f, 0.f, 0.f, 0.f);
#pragma unroll 4
        for (int k = 0; k < 384; k++) {
            float p  = srow[k];
            float4 v = *(float4*)(Vs + k * KS_STRIDE + dg);
            o.x += p * v.x; o.y += p * v.y; o.z += p * v.z; o.w += p * v.w;
        }
        size_t token = base + qbase + q;
        float4 g = *(const float4*)(g_gt + token * CDIM + col0 + dg);
        o.x *= g.x; o.y *= g.y; o.z *= g.z; o.w *= g.w;
        *(float4*)(g_og + token * CDIM + col0 + dg) = o;
    }
}

// =====================================================================
// launch
// =====================================================================
extern "C" void kernel_launch(void* const* d_in, const int* in_sizes, int n_in,
                              void* d_out, int out_size)
{
    const float* x    = (const float*)d_in[0];
    const float* mask = (const float*)d_in[1];
    const float* lnw  = (const float*)d_in[2];
    const float* lnb  = (const float*)d_in[3];
    const float* wz   = (const float*)d_in[4];
    const float* bz   = (const float*)d_in[5];
    const float* wq   = (const float*)d_in[6];
    const float* wk   = (const float*)d_in[7];
    const float* wv   = (const float*)d_in[8];
    const float* wg   = (const float*)d_in[9];
    const float* bg   = (const float*)d_in[10];
    const float* wo   = (const float*)d_in[11];
    const float* bo   = (const float*)d_in[12];
    float* out = (float*)d_out;

    float *p_xln, *p_q, *p_k, *p_v, *p_g, *p_og;
    cudaGetSymbolAddress((void**)&p_xln, g_xln);
    cudaGetSymbolAddress((void**)&p_q,   g_q);
    cudaGetSymbolAddress((void**)&p_k,   g_k);
    cudaGetSymbolAddress((void**)&p_v,   g_v);
    cudaGetSymbolAddress((void**)&p_g,   g_gt);
    cudaGetSymbolAddress((void**)&p_og,  g_og);

    cudaFuncSetAttribute(gemm128, cudaFuncAttributeMaxDynamicSharedMemorySize,
                         GEMM_SMEM_BYTES);
    cudaFuncSetAttribute(attn_kernel, cudaFuncAttributeMaxDynamicSharedMemorySize,
                         ATTN_SMEM_BYTES);

    // 1) LayerNorm + tri-bias
    ln_z_kernel<<<NTOK / 8, 256>>>(x, lnw, lnb, wz, bz);

    // 2) projections
    gemm128<<<NTOK / 128, 256, GEMM_SMEM_BYTES>>>(p_xln, wq, p_q, nullptr, 0);
    gemm128<<<NTOK / 128, 256, GEMM_SMEM_BYTES>>>(p_xln, wk, p_k, nullptr, 1);
    gemm128<<<NTOK / 128, 256, GEMM_SMEM_BYTES>>>(p_xln, wv, p_v, nullptr, 1);
    gemm128<<<NTOK / 128, 256, GEMM_SMEM_BYTES>>>(p_xln, wg, p_g, bg, 3);

    // 3) attention (+ gate fused)
    attn_kernel<<<dim3(12, HEADS, IDIM), 256, ATTN_SMEM_BYTES>>>(mask);

    // 4) output projection
    gemm128<<<NTOK / 128, 256, GEMM_SMEM_BYTES>>>(p_og, wo, out, bo, 4);
}

// round 2
// speedup vs baseline: 1.3303x; 1.3303x over previous
#include <cuda_runtime.h>
#include <math.h>

// Problem constants
#define IDIM   384
#define JDIM   384
#define NTOK   (IDIM*JDIM)      // 147456
#define CDIM   128
#define HEADS  4
#define HDIM   32
#define QSCALE 0.17677669529663687f   // 1/sqrt(32)

// -------- scratch (device globals; no allocation allowed) --------
__device__ float g_xln[(size_t)NTOK*CDIM];
__device__ float g_q  [(size_t)NTOK*CDIM];
__device__ float g_k  [(size_t)NTOK*CDIM];
__device__ float g_v  [(size_t)NTOK*CDIM];
__device__ float g_gt [(size_t)NTOK*CDIM];
__device__ float g_og [(size_t)NTOK*CDIM];
__device__ float g_tb [(size_t)HEADS*NTOK];   // [h][q*384 + k]

// ---------- packed f32x2 helpers ----------
__device__ __forceinline__ unsigned long long pack2(float x, float y) {
    unsigned long long r;
    asm("mov.b64 %0, {%1,%2};" : "=l"(r) : "f"(x), "f"(y));
    return r;
}
__device__ __forceinline__ void fma2(unsigned long long& d,
                                     unsigned long long a,
                                     unsigned long long b) {
    asm("fma.rn.f32x2 %0, %1, %2, %3;" : "=l"(d) : "l"(a), "l"(b), "l"(d));
}
__device__ __forceinline__ float2 unpack2(unsigned long long v) {
    float2 f;
    asm("mov.b64 {%0,%1}, %2;" : "=f"(f.x), "=f"(f.y) : "l"(v));
    return f;
}

// =====================================================================
// Kernel 1: LayerNorm + tri-bias projection (x @ wz + bz)
// =====================================================================
__global__ __launch_bounds__(256) void ln_z_kernel(
    const float* __restrict__ x,
    const float* __restrict__ lnw, const float* __restrict__ lnb,
    const float* __restrict__ wz,  const float* __restrict__ bz)
{
    int warp = threadIdx.x >> 5;
    int lane = threadIdx.x & 31;
    size_t token = (size_t)blockIdx.x * 8 + warp;

    float4 xv = ((const float4*)(x + token * CDIM))[lane];

    float s = xv.x + xv.y + xv.z + xv.w;
#pragma unroll
    for (int m = 16; m; m >>= 1) s += __shfl_xor_sync(0xffffffffu, s, m);
    float mu = s * (1.0f / 128.0f);

    float dx = xv.x - mu, dy = xv.y - mu, dz = xv.z - mu, dw = xv.w - mu;
    float s2 = dx*dx + dy*dy + dz*dz + dw*dw;
#pragma unroll
    for (int m = 16; m; m >>= 1) s2 += __shfl_xor_sync(0xffffffffu, s2, m);
    float rstd = rsqrtf(s2 * (1.0f / 128.0f) + 1e-5f);

    float4 wv = ((const float4*)lnw)[lane];
    float4 bv = ((const float4*)lnb)[lane];
    float4 y;
    y.x = dx * rstd * wv.x + bv.x;
    y.y = dy * rstd * wv.y + bv.y;
    y.z = dz * rstd * wv.z + bv.z;
    y.w = dw * rstd * wv.w + bv.w;
    ((float4*)(g_xln + token * CDIM))[lane] = y;

    const float4* wzr = (const float4*)wz;
    int c = lane * 4;
    float4 w0 = wzr[c], w1 = wzr[c+1], w2 = wzr[c+2], w3 = wzr[c+3];
    float4 a;
    a.x = y.x*w0.x + y.y*w1.x + y.z*w2.x + y.w*w3.x;
    a.y = y.x*w0.y + y.y*w1.y + y.z*w2.y + y.w*w3.y;
    a.z = y.x*w0.z + y.y*w1.z + y.z*w2.z + y.w*w3.z;
    a.w = y.x*w0.w + y.y*w1.w + y.z*w2.w + y.w*w3.w;
#pragma unroll
    for (int m = 16; m; m >>= 1) {
        a.x += __shfl_xor_sync(0xffffffffu, a.x, m);
        a.y += __shfl_xor_sync(0xffffffffu, a.y, m);
        a.z += __shfl_xor_sync(0xffffffffu, a.z, m);
        a.w += __shfl_xor_sync(0xffffffffu, a.w, m);
    }
    if (lane == 0) {
        g_tb[0*(size_t)NTOK + token] = a.x + bz[0];
        g_tb[1*(size_t)NTOK + token] = a.y + bz[1];
        g_tb[2*(size_t)NTOK + token] = a.z + bz[2];
        g_tb[3*(size_t)NTOK + token] = a.w + bz[3];
    }
}

// =====================================================================
// Shared GEMM micro-kernel pieces (f32x2 inner product)
// =====================================================================
#define GEMM_AS_STRIDE 132
#define GEMM_SMEM_BYTES ((128*GEMM_AS_STRIDE + 128*128)*4)

// compute 8x8 tile into packed acc2[8][4]; As/Bs in smem
__device__ __forceinline__ void gemm_tile_compute(
    const float* As, const float* Bs, int tm, int tn,
    unsigned long long acc2[8][4])
{
#pragma unroll
    for (int i = 0; i < 8; i++)
#pragma unroll
        for (int j = 0; j < 4; j++) acc2[i][j] = 0ull;

    for (int k4 = 0; k4 < 128; k4 += 4) {
        float4 am[8];
#pragma unroll
        for (int i = 0; i < 8; i++)
            am[i] = *(const float4*)(As + (tm + i) * GEMM_AS_STRIDE + k4);
#pragma unroll
        for (int kk = 0; kk < 4; kk++) {
            const float* brow = Bs + (k4 + kk) * 128 + tn;
            ulonglong2 b01 = *(const ulonglong2*)(brow);
            ulonglong2 b23 = *(const ulonglong2*)(brow + 4);
            unsigned long long bv[4] = {b01.x, b01.y, b23.x, b23.y};
#pragma unroll
            for (int i = 0; i < 8; i++) {
                float a = (kk == 0) ? am[i].x : (kk == 1) ? am[i].y
                        : (kk == 2) ? am[i].z : am[i].w;
                unsigned long long a2 = pack2(a, a);
#pragma unroll
                for (int j = 0; j < 4; j++) fma2(acc2[i][j], a2, bv[j]);
            }
        }
    }
}

// =====================================================================
// Kernel 2a: fused 4-way projection (q, k, v, gate) — A tile loaded once
// =====================================================================
__global__ __launch_bounds__(256) void proj4_kernel(
    const float* __restrict__ A,
    const float* __restrict__ wq, const float* __restrict__ wk,
    const float* __restrict__ wv, const float* __restrict__ wg,
    const float* __restrict__ bg)
{
    extern __shared__ float sm[];
    float* As = sm;
    float* Bs = sm + 128 * GEMM_AS_STRIDE;

    int tid = threadIdx.x;
    size_t rowbase = (size_t)blockIdx.x * 128;

#pragma unroll
    for (int it = 0; it < 16; it++) {
        int idx = tid + it * 256;
        int m  = idx >> 5;
        int k4 = (idx & 31) << 2;
        *(float4*)(As + m * GEMM_AS_STRIDE + k4) =
            *(const float4*)(A + (rowbase + m) * CDIM + k4);
    }

    int tm = (tid >> 4) << 3;
    int tn = (tid & 15) << 3;

    const float* Ws[4] = {wq, wk, wv, wg};
    float* Os[4];
    Os[0] = g_q; Os[1] = g_k; Os[2] = g_v; Os[3] = g_gt;

    for (int wi = 0; wi < 4; wi++) {
        __syncthreads();
        const float* W = Ws[wi];
#pragma unroll
        for (int it = 0; it < 16; it++) {
            int idx = tid + it * 256;
            int k  = idx >> 5;
            int n4 = (idx & 31) << 2;
            *(float4*)(Bs + k * 128 + n4) = *(const float4*)(W + k * 128 + n4);
        }
        __syncthreads();

        unsigned long long acc2[8][4];
        gemm_tile_compute(As, Bs, tm, tn, acc2);

        float bb[8];
        if (wi == 3) {
#pragma unroll
            for (int j = 0; j < 8; j++) bb[j] = bg[tn + j];
        }
        float* out = Os[wi];
#pragma unroll
        for (int i = 0; i < 8; i++) {
            float v[8];
#pragma unroll
            for (int j = 0; j < 4; j++) {
                float2 t = unpack2(acc2[i][j]);
                v[2*j] = t.x; v[2*j+1] = t.y;
            }
#pragma unroll
            for (int j = 0; j < 8; j++) {
                if (wi == 0) v[j] *= QSCALE;
                else if (wi == 3) v[j] = 1.0f / (1.0f + __expf(-(v[j] + bb[j])));
            }
            float* orow = out + (rowbase + tm + i) * CDIM + tn;
            *(float4*)(orow)     = make_float4(v[0], v[1], v[2], v[3]);
            *(float4*)(orow + 4) = make_float4(v[4], v[5], v[6], v[7]);
        }
    }
}

// =====================================================================
// Kernel 2b: output projection GEMM (+bias)
// =====================================================================
__global__ __launch_bounds__(256) void gemm_out(
    const float* __restrict__ A, const float* __restrict__ W,
    float* __restrict__ out, const float* __restrict__ bias)
{
    extern __shared__ float sm[];
    float* As = sm;
    float* Bs = sm + 128 * GEMM_AS_STRIDE;

    int tid = threadIdx.x;
    size_t rowbase = (size_t)blockIdx.x * 128;

#pragma unroll
    for (int it = 0; it < 16; it++) {
        int idx = tid + it * 256;
        int m  = idx >> 5;
        int k4 = (idx & 31) << 2;
        *(float4*)(As + m * GEMM_AS_STRIDE + k4) =
            *(const float4*)(A + (rowbase + m) * CDIM + k4);
    }
#pragma unroll
    for (int it = 0; it < 16; it++) {
        int idx = tid + it * 256;
        int k  = idx >> 5;
        int n4 = (idx & 31) << 2;
        *(float4*)(Bs + k * 128 + n4) = *(const float4*)(W + k * 128 + n4);
    }
    __syncthreads();

    int tm = (tid >> 4) << 3;
    int tn = (tid & 15) << 3;

    unsigned long long acc2[8][4];
    gemm_tile_compute(As, Bs, tm, tn, acc2);

    float bb[8];
#pragma unroll
    for (int j = 0; j < 8; j++) bb[j] = bias[tn + j];
#pragma unroll
    for (int i = 0; i < 8; i++) {
        float v[8];
#pragma unroll
        for (int j = 0; j < 4; j++) {
            float2 t = unpack2(acc2[i][j]);
            v[2*j] = t.x + bb[2*j]; v[2*j+1] = t.y + bb[2*j+1];
        }
        float* orow = out + (rowbase + tm + i) * CDIM + tn;
        *(float4*)(orow)     = make_float4(v[0], v[1], v[2], v[3]);
        *(float4*)(orow + 4) = make_float4(v[4], v[5], v[6], v[7]);
    }
}

// =====================================================================
// Kernel 3: attention per (q-tile=64, head, i-row), 512 threads
//   Kst: transposed K [32 d][384 k] stride 386
//   S:   [64 q][384 k] stride 386 (reused as reduction buffer after PV)
// =====================================================================
#define QT        64
#define KST       386
#define SST       386
#define VS_STRIDE 36
#define QS_STRIDE 36
#define OFF_KST   (QT*QS_STRIDE)              // 2304
#define OFF_VS    (OFF_KST + 32*KST)          // 14656
#define OFF_S     (OFF_VS + 384*VS_STRIDE)    // 28480
#define OFF_MS    (OFF_S + QT*SST)            // 53184
#define ATTN_SMEM_FLOATS (OFF_MS + 384)       // 53568
#define ATTN_SMEM_BYTES  (ATTN_SMEM_FLOATS*4) // 214272

__global__ __launch_bounds__(512) void attn_kernel(const float* __restrict__ mask)
{
    extern __shared__ float sm[];
    float* Qs  = sm;            // [64][36]
    float* Kst = sm + OFF_KST;  // [32][386]
    float* Vs  = sm + OFF_VS;   // [384][36]
    float* S   = sm + OFF_S;    // [64][386]
    float* Ms  = sm + OFF_MS;   // [384]

    int tid = threadIdx.x;
    int qt  = blockIdx.x;                 // 0..5
    int h   = blockIdx.y;                 // 0..3
    int i   = blockIdx.z;                 // 0..383
    size_t base = (size_t)i * JDIM;
    int col0 = h * HDIM;
    int qbase = qt * QT;

    // ---- fills ----
    {
        int q  = tid >> 3;
        int d4 = (tid & 7) << 2;
        *(float4*)(Qs + q * QS_STRIDE + d4) =
            *(const float4*)(g_q + (base + qbase + q) * CDIM + col0 + d4);
    }
#pragma unroll
    for (int it = 0; it < 6; it++) {
        int idx = tid + it * 512;
        int k  = idx >> 3;
        int d4 = (idx & 7) << 2;
        float4 kv = *(const float4*)(g_k + (base + k) * CDIM + col0 + d4);
        Kst[(d4+0) * KST + k] = kv.x;
        Kst[(d4+1) * KST + k] = kv.y;
        Kst[(d4+2) * KST + k] = kv.z;
        Kst[(d4+3) * KST + k] = kv.w;
        *(float4*)(Vs + k * VS_STRIDE + d4) =
            *(const float4*)(g_v + (base + k) * CDIM + col0 + d4);
    }
    if (tid < 384) Ms[tid] = 1e9f * (mask[base + tid] - 1.0f);
    __syncthreads();

    // ---- QK^T: warp qg handles q rows {qg, qg+16, qg+32, qg+48},
    //      lane kg handles k pairs k0 = 2*kg + 64*ikp ----
    int qg = tid >> 5;   // 0..15 (warp id)
    int kg = tid & 31;

    unsigned long long acc2[4][6];
#pragma unroll
    for (int a = 0; a < 4; a++)
#pragma unroll
        for (int b = 0; b < 6; b++) acc2[a][b] = 0ull;

#pragma unroll
    for (int d4 = 0; d4 < 32; d4 += 4) {
        float4 qf[4];
#pragma unroll
        for (int iq = 0; iq < 4; iq++)
            qf[iq] = *(const float4*)(Qs + (qg + 16*iq) * QS_STRIDE + d4);
#pragma unroll
        for (int dd = 0; dd < 4; dd++) {
            unsigned long long q2[4];
#pragma unroll
            for (int iq = 0; iq < 4; iq++) {
                float qv = (dd == 0) ? qf[iq].x : (dd == 1) ? qf[iq].y
                         : (dd == 2) ? qf[iq].z : qf[iq].w;
                q2[iq] = pack2(qv, qv);
            }
            const float* krow = Kst + (d4 + dd) * KST + 2*kg;
#pragma unroll
            for (int ikp = 0; ikp < 6; ikp++) {
                unsigned long long k2 = *(const unsigned long long*)(krow + 64*ikp);
#pragma unroll
                for (int iq = 0; iq < 4; iq++) fma2(acc2[iq][ikp], q2[iq], k2);
            }
        }
    }

    // epilogue: add tri-bias + mask-bias, store to S
    const float* tbh = g_tb + (size_t)h * NTOK;
#pragma unroll
    for (int iq = 0; iq < 4; iq++) {
        int q = qg + 16*iq;
        const float* tbrow = tbh + (size_t)(qbase + q) * JDIM;
#pragma unroll
        for (int ikp = 0; ikp < 6; ikp++) {
            int k0 = 2*kg + 64*ikp;
            float2 t  = unpack2(acc2[iq][ikp]);
            float2 tb = *(const float2*)(tbrow + k0);
            float2 m2 = *(const float2*)(Ms + k0);
            float2 o;
            o.x = t.x + tb.x + m2.x;
            o.y = t.y + tb.y + m2.y;
            *(float2*)(S + q * SST + k0) = o;
        }
    }
    __syncthreads();

    // ---- softmax (8 threads per row, 64 rows) ----
    {
        int row = tid >> 3;
        int sub = tid & 7;
        float* srow = S + row * SST;
        float mx = -1e30f;
#pragma unroll
        for (int t = 0; t < 48; t++) mx = fmaxf(mx, srow[sub + 8*t]);
#pragma unroll
        for (int m = 4; m; m >>= 1)
            mx = fmaxf(mx, __shfl_xor_sync(0xffffffffu, mx, m));
        float sum = 0.0f;
#pragma unroll
        for (int t = 0; t < 48; t++) {
            float e = __expf(srow[sub + 8*t] - mx);
            srow[sub + 8*t] = e;
            sum += e;
        }
#pragma unroll
        for (int m = 4; m; m >>= 1)
            sum += __shfl_xor_sync(0xffffffffu, sum, m);
        float inv = 1.0f / sum;
#pragma unroll
        for (int t = 0; t < 48; t++) srow[sub + 8*t] *= inv;
    }
    __syncthreads();

    // ---- O = P V: 4 q-rows share each V float4; k split 4 ways ----
    int kset = tid >> 7;          // 0..3
    int r    = tid & 127;
    int qg2  = r >> 3;            // 0..15
    int dg   = r & 7;             // 0..7
    int q0   = qg2 * 4;
    int d0   = dg * 4;
    int ks   = kset * 96;

    unsigned long long o2[4][2];
#pragma unroll
    for (int a = 0; a < 4; a++) { o2[a][0] = 0ull; o2[a][1] = 0ull; }

#pragma unroll 2
    for (int k = ks; k < ks + 96; k++) {
        ulonglong2 v2 = *(const ulonglong2*)(Vs + k * VS_STRIDE + d0);
#pragma unroll
        for (int iq = 0; iq < 4; iq++) {
            float p = S[(q0 + iq) * SST + k];
            unsigned long long p2 = pack2(p, p);
            fma2(o2[iq][0], p2, v2.x);
            fma2(o2[iq][1], p2, v2.y);
        }
    }
    __syncthreads();   // all PV reads of S done

    // partial reduction through S region (reused)
    if (kset > 0) {
#pragma unroll
        for (int iq = 0; iq < 4; iq++) {
            int q = q0 + iq;
            float2 a0 = unpack2(o2[iq][0]);
            float2 a1 = unpack2(o2[iq][1]);
            float* rp = S + (size_t)(kset - 1) * 2048 + q * 32 + d0;
            *(float2*)(rp)     = a0;
            *(float2*)(rp + 2) = a1;
        }
    }
    __syncthreads();

    if (kset == 0) {
#pragma unroll
        for (int iq = 0; iq < 4; iq++) {
            int q = q0 + iq;
            float2 a0 = unpack2(o2[iq][0]);
            float2 a1 = unpack2(o2[iq][1]);
#pragma unroll
            for (int p = 0; p < 3; p++) {
                const float* rp = S + (size_t)p * 2048 + q * 32 + d0;
                float2 b0 = *(const float2*)(rp);
                float2 b1 = *(const float2*)(rp + 2);
                a0.x += b0.x; a0.y += b0.y;
                a1.x += b1.x; a1.y += b1.y;
            }
            size_t token = base + qbase + q;
            float4 g = *(const float4*)(g_gt + token * CDIM + col0 + d0);
            float4 o;
            o.x = a0.x * g.x; o.y = a0.y * g.y;
            o.z = a1.x * g.z; o.w = a1.y * g.w;
            *(float4*)(g_og + token * CDIM + col0 + d0) = o;
        }
    }
}

// =====================================================================
// launch
// =====================================================================
extern "C" void kernel_launch(void* const* d_in, const int* in_sizes, int n_in,
                              void* d_out, int out_size)
{
    const float* x    = (const float*)d_in[0];
    const float* mask = (const float*)d_in[1];
    const float* lnw  = (const float*)d_in[2];
    const float* lnb  = (const float*)d_in[3];
    const float* wz   = (const float*)d_in[4];
    const float* bz   = (const float*)d_in[5];
    const float* wq   = (const float*)d_in[6];
    const float* wk   = (const float*)d_in[7];
    const float* wv   = (const float*)d_in[8];
    const float* wg   = (const float*)d_in[9];
    const float* bg   = (const float*)d_in[10];
    const float* wo   = (const float*)d_in[11];
    const float* bo   = (const float*)d_in[12];
    float* out = (float*)d_out;

    float *p_xln, *p_og;
    cudaGetSymbolAddress((void**)&p_xln, g_xln);
    cudaGetSymbolAddress((void**)&p_og,  g_og);

    cudaFuncSetAttribute(proj4_kernel, cudaFuncAttributeMaxDynamicSharedMemorySize,
                         GEMM_SMEM_BYTES);
    cudaFuncSetAttribute(gemm_out, cudaFuncAttributeMaxDynamicSharedMemorySize,
                         GEMM_SMEM_BYTES);
    cudaFuncSetAttribute(attn_kernel, cudaFuncAttributeMaxDynamicSharedMemorySize,
                         ATTN_SMEM_BYTES);

    // 1) LayerNorm + tri-bias
    ln_z_kernel<<<NTOK / 8, 256>>>(x, lnw, lnb, wz, bz);

    // 2) fused projections q/k/v/gate
    proj4_kernel<<<NTOK / 128, 256, GEMM_SMEM_BYTES>>>(p_xln, wq, wk, wv, wg, bg);

    // 3) attention (+ gate fused)
    attn_kernel<<<dim3(6, HEADS, IDIM), 512, ATTN_SMEM_BYTES>>>(mask);

    // 4) output projection
    gemm_out<<<NTOK / 128, 256, GEMM_SMEM_BYTES>>>(p_og, wo, out, bo);
}

// round 4
// speedup vs baseline: 1.6810x; 1.2637x over previous
#include <cuda_runtime.h>
#include <math.h>
#include <stdint.h>

// Problem constants
#define IDIM   384
#define JDIM   384
#define NTOK   (IDIM*JDIM)      // 147456
#define CDIM   128
#define HEADS  4
#define HDIM   32
#define QSCALE 0.17677669529663687f   // 1/sqrt(32)

// -------- scratch (device globals; no allocation allowed) --------
__device__ float g_xln[(size_t)NTOK*CDIM];
__device__ float g_q  [(size_t)NTOK*CDIM];
__device__ float g_k  [(size_t)NTOK*CDIM];
__device__ float g_v  [(size_t)NTOK*CDIM];
__device__ float g_gt [(size_t)NTOK*CDIM];
__device__ float g_og [(size_t)NTOK*CDIM];
__device__ float g_tb [(size_t)HEADS*NTOK];   // [h][q*384 + k]

// ---------- packed f32x2 helpers (SIMT GEMM path) ----------
__device__ __forceinline__ unsigned long long pack2(float x, float y) {
    unsigned long long r;
    asm("mov.b64 %0, {%1,%2};" : "=l"(r) : "f"(x), "f"(y));
    return r;
}
__device__ __forceinline__ void fma2(unsigned long long& d,
                                     unsigned long long a,
                                     unsigned long long b) {
    asm("fma.rn.f32x2 %0, %1, %2, %3;" : "=l"(d) : "l"(a), "l"(b), "l"(d));
}
__device__ __forceinline__ float2 unpack2(unsigned long long v) {
    float2 f;
    asm("mov.b64 {%0,%1}, %2;" : "=f"(f.x), "=f"(f.y) : "l"(v));
    return f;
}

// ---------- tf32 mma.sync helpers ----------
__device__ __forceinline__ uint32_t f2tf(float x) {
    uint32_t r;
    asm("cvt.rna.tf32.f32 %0, %1;" : "=r"(r) : "f"(x));
    return r;
}
__device__ __forceinline__ void mma_tf32(float* d,
                                         uint32_t a0, uint32_t a1,
                                         uint32_t a2, uint32_t a3,
                                         uint32_t b0, uint32_t b1) {
    asm volatile(
        "mma.sync.aligned.m16n8k8.row.col.f32.tf32.tf32.f32 "
        "{%0,%1,%2,%3}, {%4,%5,%6,%7}, {%8,%9}, {%0,%1,%2,%3};"
        : "+f"(d[0]), "+f"(d[1]), "+f"(d[2]), "+f"(d[3])
        : "r"(a0), "r"(a1), "r"(a2), "r"(a3), "r"(b0), "r"(b1));
}

// =====================================================================
// Kernel 1: LayerNorm + tri-bias projection (x @ wz + bz)
// =====================================================================
__global__ __launch_bounds__(256) void ln_z_kernel(
    const float* __restrict__ x,
    const float* __restrict__ lnw, const float* __restrict__ lnb,
    const float* __restrict__ wz,  const float* __restrict__ bz)
{
    int warp = threadIdx.x >> 5;
    int lane = threadIdx.x & 31;
    size_t token = (size_t)blockIdx.x * 8 + warp;

    float4 xv = ((const float4*)(x + token * CDIM))[lane];

    float s = xv.x + xv.y + xv.z + xv.w;
#pragma unroll
    for (int m = 16; m; m >>= 1) s += __shfl_xor_sync(0xffffffffu, s, m);
    float mu = s * (1.0f / 128.0f);

    float dx = xv.x - mu, dy = xv.y - mu, dz = xv.z - mu, dw = xv.w - mu;
    float s2 = dx*dx + dy*dy + dz*dz + dw*dw;
#pragma unroll
    for (int m = 16; m; m >>= 1) s2 += __shfl_xor_sync(0xffffffffu, s2, m);
    float rstd = rsqrtf(s2 * (1.0f / 128.0f) + 1e-5f);

    float4 wv = ((const float4*)lnw)[lane];
    float4 bv = ((const float4*)lnb)[lane];
    float4 y;
    y.x = dx * rstd * wv.x + bv.x;
    y.y = dy * rstd * wv.y + bv.y;
    y.z = dz * rstd * wv.z + bv.z;
    y.w = dw * rstd * wv.w + bv.w;
    ((float4*)(g_xln + token * CDIM))[lane] = y;

    const float4* wzr = (const float4*)wz;
    int c = lane * 4;
    float4 w0 = wzr[c], w1 = wzr[c+1], w2 = wzr[c+2], w3 = wzr[c+3];
    float4 a;
    a.x = y.x*w0.x + y.y*w1.x + y.z*w2.x + y.w*w3.x;
    a.y = y.x*w0.y + y.y*w1.y + y.z*w2.y + y.w*w3.y;
    a.z = y.x*w0.z + y.y*w1.z + y.z*w2.z + y.w*w3.z;
    a.w = y.x*w0.w + y.y*w1.w + y.z*w2.w + y.w*w3.w;
#pragma unroll
    for (int m = 16; m; m >>= 1) {
        a.x += __shfl_xor_sync(0xffffffffu, a.x, m);
        a.y += __shfl_xor_sync(0xffffffffu, a.y, m);
        a.z += __shfl_xor_sync(0xffffffffu, a.z, m);
        a.w += __shfl_xor_sync(0xffffffffu, a.w, m);
    }
    if (lane == 0) {
        g_tb[0*(size_t)NTOK + token] = a.x + bz[0];
        g_tb[1*(size_t)NTOK + token] = a.y + bz[1];
        g_tb[2*(size_t)NTOK + token] = a.z + bz[2];
        g_tb[3*(size_t)NTOK + token] = a.w + bz[3];
    }
}

// =====================================================================
// SIMT GEMM (f32x2) for projections + output projection
// =====================================================================
#define GEMM_AS_STRIDE 132
#define GEMM_SMEM_BYTES ((128*GEMM_AS_STRIDE + 128*128)*4)

__device__ __forceinline__ void gemm_tile_compute(
    const float* As, const float* Bs, int tm, int tn,
    unsigned long long acc2[8][4])
{
#pragma unroll
    for (int i = 0; i < 8; i++)
#pragma unroll
        for (int j = 0; j < 4; j++) acc2[i][j] = 0ull;

    for (int k4 = 0; k4 < 128; k4 += 4) {
        float4 am[8];
#pragma unroll
        for (int i = 0; i < 8; i++)
            am[i] = *(const float4*)(As + (tm + i) * GEMM_AS_STRIDE + k4);
#pragma unroll
        for (int kk = 0; kk < 4; kk++) {
            const float* brow = Bs + (k4 + kk) * 128 + tn;
            ulonglong2 b01 = *(const ulonglong2*)(brow);
            ulonglong2 b23 = *(const ulonglong2*)(brow + 4);
            unsigned long long bv[4] = {b01.x, b01.y, b23.x, b23.y};
#pragma unroll
            for (int i = 0; i < 8; i++) {
                float a = (kk == 0) ? am[i].x : (kk == 1) ? am[i].y
                        : (kk == 2) ? am[i].z : am[i].w;
                unsigned long long a2 = pack2(a, a);
#pragma unroll
                for (int j = 0; j < 4; j++) fma2(acc2[i][j], a2, bv[j]);
            }
        }
    }
}

__global__ __launch_bounds__(256) void proj4_kernel(
    const float* __restrict__ A,
    const float* __restrict__ wq, const float* __restrict__ wk,
    const float* __restrict__ wv, const float* __restrict__ wg,
    const float* __restrict__ bg)
{
    extern __shared__ float sm[];
    float* As = sm;
    float* Bs = sm + 128 * GEMM_AS_STRIDE;

    int tid = threadIdx.x;
    size_t rowbase = (size_t)blockIdx.x * 128;

#pragma unroll
    for (int it = 0; it < 16; it++) {
        int idx = tid + it * 256;
        int m  = idx >> 5;
        int k4 = (idx & 31) << 2;
        *(float4*)(As + m * GEMM_AS_STRIDE + k4) =
            *(const float4*)(A + (rowbase + m) * CDIM + k4);
    }

    int tm = (tid >> 4) << 3;
    int tn = (tid & 15) << 3;

    const float* Ws[4] = {wq, wk, wv, wg};
    float* Os[4];
    Os[0] = g_q; Os[1] = g_k; Os[2] = g_v; Os[3] = g_gt;

    for (int wi = 0; wi < 4; wi++) {
        __syncthreads();
        const float* W = Ws[wi];
#pragma unroll
        for (int it = 0; it < 16; it++) {
            int idx = tid + it * 256;
            int k  = idx >> 5;
            int n4 = (idx & 31) << 2;
            *(float4*)(Bs + k * 128 + n4) = *(const float4*)(W + k * 128 + n4);
        }
        __syncthreads();

        unsigned long long acc2[8][4];
        gemm_tile_compute(As, Bs, tm, tn, acc2);

        float bb[8];
        if (wi == 3) {
#pragma unroll
            for (int j = 0; j < 8; j++) bb[j] = bg[tn + j];
        }
        float* out = Os[wi];
#pragma unroll
        for (int i = 0; i < 8; i++) {
            float v[8];
#pragma unroll
            for (int j = 0; j < 4; j++) {
                float2 t = unpack2(acc2[i][j]);
                v[2*j] = t.x; v[2*j+1] = t.y;
            }
#pragma unroll
            for (int j = 0; j < 8; j++) {
                if (wi == 0) v[j] *= QSCALE;
                else if (wi == 3) v[j] = 1.0f / (1.0f + __expf(-(v[j] + bb[j])));
            }
            float* orow = out + (rowbase + tm + i) * CDIM + tn;
            *(float4*)(orow)     = make_float4(v[0], v[1], v[2], v[3]);
            *(float4*)(orow + 4) = make_float4(v[4], v[5], v[6], v[7]);
        }
    }
}

__global__ __launch_bounds__(256) void gemm_out(
    const float* __restrict__ A, const float* __restrict__ W,
    float* __restrict__ out, const float* __restrict__ bias)
{
    extern __shared__ float sm[];
    float* As = sm;
    float* Bs = sm + 128 * GEMM_AS_STRIDE;

    int tid = threadIdx.x;
    size_t rowbase = (size_t)blockIdx.x * 128;

#pragma unroll
    for (int it = 0; it < 16; it++) {
        int idx = tid + it * 256;
        int m  = idx >> 5;
        int k4 = (idx & 31) << 2;
        *(float4*)(As + m * GEMM_AS_STRIDE + k4) =
            *(const float4*)(A + (rowbase + m) * CDIM + k4);
    }
#pragma unroll
    for (int it = 0; it < 16; it++) {
        int idx = tid + it * 256;
        int k  = idx >> 5;
        int n4 = (idx & 31) << 2;
        *(float4*)(Bs + k * 128 + n4) = *(const float4*)(W + k * 128 + n4);
    }
    __syncthreads();

    int tm = (tid >> 4) << 3;
    int tn = (tid & 15) << 3;

    unsigned long long acc2[8][4];
    gemm_tile_compute(As, Bs, tm, tn, acc2);

    float bb[8];
#pragma unroll
    for (int j = 0; j < 8; j++) bb[j] = bias[tn + j];
#pragma unroll
    for (int i = 0; i < 8; i++) {
        float v[8];
#pragma unroll
        for (int j = 0; j < 4; j++) {
            float2 t = unpack2(acc2[i][j]);
            v[2*j] = t.x + bb[2*j]; v[2*j+1] = t.y + bb[2*j+1];
        }
        float* orow = out + (rowbase + tm + i) * CDIM + tn;
        *(float4*)(orow)     = make_float4(v[0], v[1], v[2], v[3]);
        *(float4*)(orow + 4) = make_float4(v[4], v[5], v[6], v[7]);
    }
}

// =====================================================================
// Kernel 3: tf32 mma.sync attention
//   CTA per (qtile=64, head, i). 256 threads / 8 warps.
// smem float layout:
//   Qs [64][36]   tf32 bits        (2304)
//   Kt [32][392]  tf32 bits, d-major (12544)
//   Vs [384][40]  tf32 bits        (15360)
//   S  [64][388]  f32 scores -> tf32 P (24832)
//   Ms [384]      mask bias        (384)
// =====================================================================
#define QT 64
#define OFF_Q   0
#define OFF_KT  2304
#define OFF_VS  (OFF_KT + 32*392)     // 14848
#define OFF_S   (OFF_VS + 384*40)     // 30208
#define OFF_MS  (OFF_S + 64*388)      // 55040
#define AT_SMEM_FLOATS (OFF_MS + 384) // 55424
#define AT_SMEM_BYTES  (AT_SMEM_FLOATS*4)  // 221696

__global__ __launch_bounds__(256) void attn_mma_kernel(const float* __restrict__ mask)
{
    extern __shared__ float sm[];
    float* Qs = sm + OFF_Q;
    float* Kt = sm + OFF_KT;
    float* Vs = sm + OFF_VS;
    float* S  = sm + OFF_S;
    float* Ms = sm + OFF_MS;
    const uint32_t* Qu = (const uint32_t*)Qs;
    const uint32_t* Ku = (const uint32_t*)Kt;
    const uint32_t* Vu = (const uint32_t*)Vs;
    const uint32_t* Su = (const uint32_t*)S;

    int tid = threadIdx.x;
    int qt  = blockIdx.x;                 // 0..5
    int h   = blockIdx.y;                 // 0..3
    int i   = blockIdx.z;                 // 0..383
    size_t base = (size_t)i * JDIM;
    int col0 = h * HDIM;
    int qbase = qt * QT;

    // ---- fill Q [64][32] (tf32) ----
    {
        int q  = tid >> 2;
        int d4 = (tid & 3) << 2;          // 0,4,8,12 then +16 below
#pragma unroll
        for (int half = 0; half < 2; half++) {
            float4 v = *(const float4*)(g_q + (base + qbase + q) * CDIM + col0 + d4 + 16*half);
            float4 o;
            o.x = __uint_as_float(f2tf(v.x));
            o.y = __uint_as_float(f2tf(v.y));
            o.z = __uint_as_float(f2tf(v.z));
            o.w = __uint_as_float(f2tf(v.w));
            *(float4*)(Qs + q * 36 + d4 + 16*half) = o;
        }
    }
    // ---- fill Kt [32 d][384 k] transposed (tf32) ----
#pragma unroll
    for (int it = 0; it < 12; it++) {
        int idx = it * 256 + tid;
        int k  = idx >> 3;
        int d4 = (idx & 7) << 2;
        float4 v = *(const float4*)(g_k + (base + k) * CDIM + col0 + d4);
        Kt[(d4+0)*392 + k] = __uint_as_float(f2tf(v.x));
        Kt[(d4+1)*392 + k] = __uint_as_float(f2tf(v.y));
        Kt[(d4+2)*392 + k] = __uint_as_float(f2tf(v.z));
        Kt[(d4+3)*392 + k] = __uint_as_float(f2tf(v.w));
    }
    // ---- fill Vs [384][32] (tf32), stride 40 ----
#pragma unroll
    for (int it = 0; it < 12; it++) {
        int idx = it * 256 + tid;
        int k  = idx >> 3;
        int d4 = (idx & 7) << 2;
        float4 v = *(const float4*)(g_v + (base + k) * CDIM + col0 + d4);
        float4 o;
        o.x = __uint_as_float(f2tf(v.x));
        o.y = __uint_as_float(f2tf(v.y));
        o.z = __uint_as_float(f2tf(v.z));
        o.w = __uint_as_float(f2tf(v.w));
        *(float4*)(Vs + k * 40 + d4) = o;
    }
    // ---- mask bias ----
    if (tid < 128) {
#pragma unroll
        for (int it = 0; it < 3; it++) {
            int k = it * 128 + tid;
            Ms[k] = 1e9f * (mask[base + k] - 1.0f);
        }
    }
    __syncthreads();

    int w    = tid >> 5;
    int lane = tid & 31;
    int gr   = lane >> 2;   // 0..7
    int tg   = lane & 3;    // 0..3

    // ================= QK^T =================
    {
        int m0 = (w & 3) * 16;
        int nh = (w >> 2) * 192;
        const float* tb0 = g_tb + (size_t)h * NTOK + (size_t)(qbase + m0 + gr) * JDIM;
        const float* tb1 = tb0 + 8 * JDIM;

#pragma unroll 1
        for (int ng = 0; ng < 3; ng++) {
            int nc = nh + ng * 64;
            float acc[8][4];
#pragma unroll
            for (int t = 0; t < 8; t++)
#pragma unroll
                for (int e = 0; e < 4; e++) acc[t][e] = 0.0f;

#pragma unroll
            for (int ks = 0; ks < 4; ks++) {
                int k0 = ks * 8;
                uint32_t a0 = Qu[(m0+gr)   * 36 + k0 + tg];
                uint32_t a1 = Qu[(m0+gr+8) * 36 + k0 + tg];
                uint32_t a2 = Qu[(m0+gr)   * 36 + k0 + tg + 4];
                uint32_t a3 = Qu[(m0+gr+8) * 36 + k0 + tg + 4];
#pragma unroll
                for (int t = 0; t < 8; t++) {
                    int n0 = nc + t * 8;
                    uint32_t b0 = Ku[(k0+tg)   * 392 + n0 + gr];
                    uint32_t b1 = Ku[(k0+tg+4) * 392 + n0 + gr];
                    mma_tf32(acc[t], a0, a1, a2, a3, b0, b1);
                }
            }
            // epilogue: add biases, write S
#pragma unroll
            for (int t = 0; t < 8; t++) {
                int col = nc + t * 8 + tg * 2;
                float2 tA = *(const float2*)(tb0 + col);
                float2 tB = *(const float2*)(tb1 + col);
                float2 mm = *(const float2*)(Ms + col);
                float2 s0, s1;
                s0.x = acc[t][0] + tA.x + mm.x;
                s0.y = acc[t][1] + tA.y + mm.y;
                s1.x = acc[t][2] + tB.x + mm.x;
                s1.y = acc[t][3] + tB.y + mm.y;
                *(float2*)(S + (m0+gr)   * 388 + col) = s0;
                *(float2*)(S + (m0+gr+8) * 388 + col) = s1;
            }
        }
    }
    __syncthreads();

    // ================= softmax (4 threads per row) =================
    {
        int row = tid >> 2;
        int sub = tid & 2;           // process float2 at sub, stride 4
        float* srow = S + row * 388;
        float mx = -1e30f;
        // each thread handles cols sub + 4*t and sub+1 + 4*t (as float2), t<96
        int c0 = (tid & 3) * 2;      // 0,2,4,6 -> stride 8 covers pairs
        (void)sub;
        float2 vbuf;
        float mxa = -1e30f, mxb = -1e30f;
#pragma unroll
        for (int t = 0; t < 48; t++) {
            vbuf = *(const float2*)(srow + c0 + 8*t);
            mxa = fmaxf(mxa, vbuf.x);
            mxb = fmaxf(mxb, vbuf.y);
        }
        mx = fmaxf(mxa, mxb);
#pragma unroll
        for (int m = 2; m; m >>= 1)
            mx = fmaxf(mx, __shfl_xor_sync(0xffffffffu, mx, m));
        float sum = 0.0f;
#pragma unroll
        for (int t = 0; t < 48; t++) {
            float2 v = *(const float2*)(srow + c0 + 8*t);
            v.x = __expf(v.x - mx);
            v.y = __expf(v.y - mx);
            sum += v.x + v.y;
            *(float2*)(srow + c0 + 8*t) = v;
        }
#pragma unroll
        for (int m = 2; m; m >>= 1)
            sum += __shfl_xor_sync(0xffffffffu, sum, m);
        float inv = 1.0f / sum;
#pragma unroll
        for (int t = 0; t < 48; t++) {
            float2 v = *(const float2*)(srow + c0 + 8*t);
            uint32_t px = f2tf(v.x * inv);
            uint32_t py = f2tf(v.y * inv);
            v.x = __uint_as_float(px);
            v.y = __uint_as_float(py);
            *(float2*)(srow + c0 + 8*t) = v;
        }
    }
    __syncthreads();

    // ================= O = P V =================
    {
        int m0 = (w & 3) * 16;
        int d0 = (w >> 2) * 16;
        float acc[2][4];
#pragma unroll
        for (int t = 0; t < 2; t++)
#pragma unroll
            for (int e = 0; e < 4; e++) acc[t][e] = 0.0f;

#pragma unroll 4
        for (int ks = 0; ks < 48; ks++) {
            int k0 = ks * 8;
            uint32_t a0 = Su[(m0+gr)   * 388 + k0 + tg];
            uint32_t a1 = Su[(m0+gr+8) * 388 + k0 + tg];
            uint32_t a2 = Su[(m0+gr)   * 388 + k0 + tg + 4];
            uint32_t a3 = Su[(m0+gr+8) * 388 + k0 + tg + 4];
#pragma unroll
            for (int t = 0; t < 2; t++) {
                int n0 = d0 + t * 8;
                uint32_t b0 = Vu[(k0+tg)   * 40 + n0 + gr];
                uint32_t b1 = Vu[(k0+tg+4) * 40 + n0 + gr];
                mma_tf32(acc[t], a0, a1, a2, a3, b0, b1);
            }
        }

        // epilogue: gate multiply, store
        size_t tok0 = base + qbase + m0 + gr;
        size_t tok1 = tok0 + 8;
#pragma unroll
        for (int t = 0; t < 2; t++) {
            int col = col0 + d0 + t * 8 + tg * 2;
            float2 gA = *(const float2*)(g_gt + tok0 * CDIM + col);
            float2 gB = *(const float2*)(g_gt + tok1 * CDIM + col);
            float2 o0, o1;
            o0.x = acc[t][0] * gA.x;  o0.y = acc[t][1] * gA.y;
            o1.x = acc[t][2] * gB.x;  o1.y = acc[t][3] * gB.y;
            *(float2*)(g_og + tok0 * CDIM + col) = o0;
            *(float2*)(g_og + tok1 * CDIM + col) = o1;
        }
    }
}

// =====================================================================
// launch
// =====================================================================
extern "C" void kernel_launch(void* const* d_in, const int* in_sizes, int n_in,
                              void* d_out, int out_size)
{
    const float* x    = (const float*)d_in[0];
    const float* mask = (const float*)d_in[1];
    const float* lnw  = (const float*)d_in[2];
    const float* lnb  = (const float*)d_in[3];
    const float* wz   = (const float*)d_in[4];
    const float* bz   = (const float*)d_in[5];
    const float* wq   = (const float*)d_in[6];
    const float* wk   = (const float*)d_in[7];
    const float* wv   = (const float*)d_in[8];
    const float* wg   = (const float*)d_in[9];
    const float* bg   = (const float*)d_in[10];
    const float* wo   = (const float*)d_in[11];
    const float* bo   = (const float*)d_in[12];
    float* out = (float*)d_out;

    float *p_xln, *p_og;
    cudaGetSymbolAddress((void**)&p_xln, g_xln);
    cudaGetSymbolAddress((void**)&p_og,  g_og);

    cudaFuncSetAttribute(proj4_kernel, cudaFuncAttributeMaxDynamicSharedMemorySize,
                         GEMM_SMEM_BYTES);
    cudaFuncSetAttribute(gemm_out, cudaFuncAttributeMaxDynamicSharedMemorySize,
                         GEMM_SMEM_BYTES);
    cudaFuncSetAttribute(attn_mma_kernel, cudaFuncAttributeMaxDynamicSharedMemorySize,
                         AT_SMEM_BYTES);

    // 1) LayerNorm + tri-bias
    ln_z_kernel<<<NTOK / 8, 256>>>(x, lnw, lnb, wz, bz);

    // 2) fused projections q/k/v/gate
    proj4_kernel<<<NTOK / 128, 256, GEMM_SMEM_BYTES>>>(p_xln, wq, wk, wv, wg, bg);

    // 3) attention on mma.sync tf32, gate fused
    attn_mma_kernel<<<dim3(6, HEADS, IDIM), 256, AT_SMEM_BYTES>>>(mask);

    // 4) output projection
    gemm_out<<<NTOK / 128, 256, GEMM_SMEM_BYTES>>>(p_og, wo, out, bo);
}

// round 5
// speedup vs baseline: 2.2924x; 1.3637x over previous
#include <cuda_runtime.h>
#include <math.h>
#include <stdint.h>

// Problem constants
#define IDIM   384
#define JDIM   384
#define NTOK   (IDIM*JDIM)      // 147456
#define CDIM   128
#define HEADS  4
#define HDIM   32
#define QSCALE 0.17677669529663687f   // 1/sqrt(32)

// -------- scratch (device globals; no allocation allowed) --------
__device__ float g_xln[(size_t)NTOK*CDIM];   // tf32 bits
__device__ float g_q  [(size_t)NTOK*CDIM];   // tf32 bits (scaled)
__device__ float g_k  [(size_t)NTOK*CDIM];   // tf32 bits
__device__ float g_v  [(size_t)NTOK*CDIM];   // tf32 bits
__device__ float g_gt [(size_t)NTOK*CDIM];   // fp32 sigmoid gate
__device__ float g_og [(size_t)NTOK*CDIM];   // tf32 bits (o * gate)
__device__ float g_tb [(size_t)HEADS*NTOK];  // fp32 [h][q*384+k]
__device__ float g_wt [4*16384];             // tf32 bits wq,wk,wv,wg
__device__ float g_wot[16384];               // tf32 bits wo

// ---------- tf32 mma.sync helpers ----------
__device__ __forceinline__ uint32_t f2tf(float x) {
    uint32_t r;
    asm("cvt.rna.tf32.f32 %0, %1;" : "=r"(r) : "f"(x));
    return r;
}
__device__ __forceinline__ void mma_tf32(float* d,
                                         uint32_t a0, uint32_t a1,
                                         uint32_t a2, uint32_t a3,
                                         uint32_t b0, uint32_t b1) {
    asm volatile(
        "mma.sync.aligned.m16n8k8.row.col.f32.tf32.tf32.f32 "
        "{%0,%1,%2,%3}, {%4,%5,%6,%7}, {%8,%9}, {%0,%1,%2,%3};"
        : "+f"(d[0]), "+f"(d[1]), "+f"(d[2]), "+f"(d[3])
        : "r"(a0), "r"(a1), "r"(a2), "r"(a3), "r"(b0), "r"(b1));
}

// =====================================================================
// Kernel 0: convert weights to tf32 (one-shot, tiny)
// =====================================================================
__global__ __launch_bounds__(256) void wconv_kernel(
    const float* __restrict__ wq, const float* __restrict__ wk,
    const float* __restrict__ wv, const float* __restrict__ wg,
    const float* __restrict__ wo)
{
    int idx = blockIdx.x * 256 + threadIdx.x;   // < 81920
    int w   = idx >> 14;
    int off = idx & 16383;
    const float* src = (w == 0) ? wq : (w == 1) ? wk : (w == 2) ? wv
                     : (w == 3) ? wg : wo;
    float v = src[off];
    float t = __uint_as_float(f2tf(v));
    if (w < 4) g_wt[idx] = t;
    else       g_wot[off] = t;
}

// =====================================================================
// Kernel 1: LayerNorm (tf32 output) + tri-bias projection (fp32)
// =====================================================================
__global__ __launch_bounds__(256) void ln_z_kernel(
    const float* __restrict__ x,
    const float* __restrict__ lnw, const float* __restrict__ lnb,
    const float* __restrict__ wz,  const float* __restrict__ bz)
{
    int warp = threadIdx.x >> 5;
    int lane = threadIdx.x & 31;
    size_t token = (size_t)blockIdx.x * 8 + warp;

    float4 xv = ((const float4*)(x + token * CDIM))[lane];

    float s = xv.x + xv.y + xv.z + xv.w;
#pragma unroll
    for (int m = 16; m; m >>= 1) s += __shfl_xor_sync(0xffffffffu, s, m);
    float mu = s * (1.0f / 128.0f);

    float dx = xv.x - mu, dy = xv.y - mu, dz = xv.z - mu, dw = xv.w - mu;
    float s2 = dx*dx + dy*dy + dz*dz + dw*dw;
#pragma unroll
    for (int m = 16; m; m >>= 1) s2 += __shfl_xor_sync(0xffffffffu, s2, m);
    float rstd = rsqrtf(s2 * (1.0f / 128.0f) + 1e-5f);

    float4 wv = ((const float4*)lnw)[lane];
    float4 bv = ((const float4*)lnb)[lane];
    float4 y;
    y.x = dx * rstd * wv.x + bv.x;
    y.y = dy * rstd * wv.y + bv.y;
    y.z = dz * rstd * wv.z + bv.z;
    y.w = dw * rstd * wv.w + bv.w;

    // tri-bias in fp32
    const float4* wzr = (const float4*)wz;
    int c = lane * 4;
    float4 w0 = wzr[c], w1 = wzr[c+1], w2 = wzr[c+2], w3 = wzr[c+3];
    float4 a;
    a.x = y.x*w0.x + y.y*w1.x + y.z*w2.x + y.w*w3.x;
    a.y = y.x*w0.y + y.y*w1.y + y.z*w2.y + y.w*w3.y;
    a.z = y.x*w0.z + y.y*w1.z + y.z*w2.z + y.w*w3.z;
    a.w = y.x*w0.w + y.y*w1.w + y.z*w2.w + y.w*w3.w;
#pragma unroll
    for (int m = 16; m; m >>= 1) {
        a.x += __shfl_xor_sync(0xffffffffu, a.x, m);
        a.y += __shfl_xor_sync(0xffffffffu, a.y, m);
        a.z += __shfl_xor_sync(0xffffffffu, a.z, m);
        a.w += __shfl_xor_sync(0xffffffffu, a.w, m);
    }
    if (lane == 0) {
        g_tb[0*(size_t)NTOK + token] = a.x + bz[0];
        g_tb[1*(size_t)NTOK + token] = a.y + bz[1];
        g_tb[2*(size_t)NTOK + token] = a.z + bz[2];
        g_tb[3*(size_t)NTOK + token] = a.w + bz[3];
    }

    // store x_ln as tf32 bits
    float4 yt;
    yt.x = __uint_as_float(f2tf(y.x));
    yt.y = __uint_as_float(f2tf(y.y));
    yt.z = __uint_as_float(f2tf(y.z));
    yt.w = __uint_as_float(f2tf(y.w));
    ((float4*)(g_xln + token * CDIM))[lane] = yt;
}

// =====================================================================
// Tensor-core projection kernels (mma.sync tf32)
// CTA: 64 rows x 128 cols, 128 threads / 4 warps, warp tile 32x64
// =====================================================================
#define PJ_LD 132
#define PJ_SMEM_BYTES ((64*PJ_LD + 128*PJ_LD)*4)   // 101376

// core compute: acc[2][8][4] over K=128
__device__ __forceinline__ void pj_compute(
    const uint32_t* Au, const uint32_t* Bu,
    int m0, int nb, int gr, int tg, float acc[2][8][4])
{
#pragma unroll
    for (int im = 0; im < 2; im++)
#pragma unroll
        for (int t = 0; t < 8; t++)
#pragma unroll
            for (int e = 0; e < 4; e++) acc[im][t][e] = 0.0f;

#pragma unroll 4
    for (int ks = 0; ks < 16; ks++) {
        int k0 = ks * 8;
        uint32_t a[2][4];
#pragma unroll
        for (int im = 0; im < 2; im++) {
            int mb = m0 + im * 16;
            a[im][0] = Au[(mb+gr)   * PJ_LD + k0 + tg];
            a[im][1] = Au[(mb+gr+8) * PJ_LD + k0 + tg];
            a[im][2] = Au[(mb+gr)   * PJ_LD + k0 + tg + 4];
            a[im][3] = Au[(mb+gr+8) * PJ_LD + k0 + tg + 4];
        }
#pragma unroll
        for (int t = 0; t < 8; t++) {
            int n0 = nb + t * 8;
            uint32_t b0 = Bu[(k0+tg)   * PJ_LD + n0 + gr];
            uint32_t b1 = Bu[(k0+tg+4) * PJ_LD + n0 + gr];
            mma_tf32(acc[0][t], a[0][0], a[0][1], a[0][2], a[0][3], b0, b1);
            mma_tf32(acc[1][t], a[1][0], a[1][1], a[1][2], a[1][3], b0, b1);
        }
    }
}

__global__ __launch_bounds__(128) void proj4_tc(
    const float* __restrict__ A, const float* __restrict__ bg)
{
    extern __shared__ float sm[];
    float* As = sm;                 // [64][132]
    float* Bs = sm + 64 * PJ_LD;    // [128][132]
    const uint32_t* Au = (const uint32_t*)As;
    const uint32_t* Bu = (const uint32_t*)Bs;

    int tid = threadIdx.x;
    size_t rowbase = (size_t)blockIdx.x * 64;

    // A fill (already tf32 bits)
#pragma unroll
    for (int it = 0; it < 16; it++) {
        int idx = it * 128 + tid;
        int m  = idx >> 5;
        int c4 = (idx & 31) << 2;
        *(float4*)(As + m * PJ_LD + c4) =
            *(const float4*)(A + (rowbase + m) * CDIM + c4);
    }

    int w = tid >> 5, lane = tid & 31;
    int gr = lane >> 2, tg = lane & 3;
    int m0 = (w & 1) * 32;
    int nb = (w >> 1) * 64;

    float* outs[4] = {g_q, g_k, g_v, g_gt};

#pragma unroll 1
    for (int wi = 0; wi < 4; wi++) {
        __syncthreads();
#pragma unroll
        for (int it = 0; it < 32; it++) {
            int idx = it * 128 + tid;
            int k  = idx >> 5;
            int n4 = (idx & 31) << 2;
            *(float4*)(Bs + k * PJ_LD + n4) =
                *(const float4*)(g_wt + wi * 16384 + k * 128 + n4);
        }
        __syncthreads();

        float acc[2][8][4];
        pj_compute(Au, Bu, m0, nb, gr, tg, acc);

        float* out = outs[wi];
#pragma unroll
        for (int im = 0; im < 2; im++) {
            size_t r0 = rowbase + m0 + im * 16 + gr;
            size_t r1 = r0 + 8;
#pragma unroll
            for (int t = 0; t < 8; t++) {
                int col = nb + t * 8 + tg * 2;
                float2 v0 = make_float2(acc[im][t][0], acc[im][t][1]);
                float2 v1 = make_float2(acc[im][t][2], acc[im][t][3]);
                if (wi == 0) {
                    v0.x = __uint_as_float(f2tf(v0.x * QSCALE));
                    v0.y = __uint_as_float(f2tf(v0.y * QSCALE));
                    v1.x = __uint_as_float(f2tf(v1.x * QSCALE));
                    v1.y = __uint_as_float(f2tf(v1.y * QSCALE));
                } else if (wi < 3) {
                    v0.x = __uint_as_float(f2tf(v0.x));
                    v0.y = __uint_as_float(f2tf(v0.y));
                    v1.x = __uint_as_float(f2tf(v1.x));
                    v1.y = __uint_as_float(f2tf(v1.y));
                } else {
                    float2 b = *(const float2*)(bg + col);
                    v0.x = 1.0f / (1.0f + __expf(-(v0.x + b.x)));
                    v0.y = 1.0f / (1.0f + __expf(-(v0.y + b.y)));
                    v1.x = 1.0f / (1.0f + __expf(-(v1.x + b.x)));
                    v1.y = 1.0f / (1.0f + __expf(-(v1.y + b.y)));
                }
                *(float2*)(out + r0 * CDIM + col) = v0;
                *(float2*)(out + r1 * CDIM + col) = v1;
            }
        }
    }
}

__global__ __launch_bounds__(128) void gemm_out_tc(
    const float* __restrict__ A, const float* __restrict__ bias,
    float* __restrict__ out)
{
    extern __shared__ float sm[];
    float* As = sm;
    float* Bs = sm + 64 * PJ_LD;
    const uint32_t* Au = (const uint32_t*)As;
    const uint32_t* Bu = (const uint32_t*)Bs;

    int tid = threadIdx.x;
    size_t rowbase = (size_t)blockIdx.x * 64;

#pragma unroll
    for (int it = 0; it < 16; it++) {
        int idx = it * 128 + tid;
        int m  = idx >> 5;
        int c4 = (idx & 31) << 2;
        *(float4*)(As + m * PJ_LD + c4) =
            *(const float4*)(A + (rowbase + m) * CDIM + c4);
    }
#pragma unroll
    for (int it = 0; it < 32; it++) {
        int idx = it * 128 + tid;
        int k  = idx >> 5;
        int n4 = (idx & 31) << 2;
        *(float4*)(Bs + k * PJ_LD + n4) =
            *(const float4*)(g_wot + k * 128 + n4);
    }
    __syncthreads();

    int w = tid >> 5, lane = tid & 31;
    int gr = lane >> 2, tg = lane & 3;
    int m0 = (w & 1) * 32;
    int nb = (w >> 1) * 64;

    float acc[2][8][4];
    pj_compute(Au, Bu, m0, nb, gr, tg, acc);

#pragma unroll
    for (int im = 0; im < 2; im++) {
        size_t r0 = rowbase + m0 + im * 16 + gr;
        size_t r1 = r0 + 8;
#pragma unroll
        for (int t = 0; t < 8; t++) {
            int col = nb + t * 8 + tg * 2;
            float2 b = *(const float2*)(bias + col);
            float2 v0 = make_float2(acc[im][t][0] + b.x, acc[im][t][1] + b.y);
            float2 v1 = make_float2(acc[im][t][2] + b.x, acc[im][t][3] + b.y);
            *(float2*)(out + r0 * CDIM + col) = v0;
            *(float2*)(out + r1 * CDIM + col) = v1;
        }
    }
}

// =====================================================================
// Kernel 3: tf32 mma.sync attention
//   CTA per (qtile=64, head, i). 256 threads / 8 warps.
//   S pre-initialized with tri-bias + mask bias; QK epilogue RMW.
//   Row max computed in QK epilogue; normalization folded into PV.
// =====================================================================
#define QT 64
#define OFF_Q   0
#define OFF_KT  2304
#define OFF_VS  (OFF_KT + 32*392)     // 14848
#define OFF_S   (OFF_VS + 384*40)     // 30208
#define OFF_MS  (OFF_S + 64*388)      // 55040
#define AT_SMEM_FLOATS (OFF_MS + 384) // 55424
#define AT_SMEM_BYTES  (AT_SMEM_FLOATS*4)  // 221696

__global__ __launch_bounds__(256) void attn_mma_kernel(const float* __restrict__ mask)
{
    extern __shared__ float sm[];
    float* Qs = sm + OFF_Q;
    float* Kt = sm + OFF_KT;
    float* Vs = sm + OFF_VS;
    float* S  = sm + OFF_S;
    float* Ms = sm + OFF_MS;          // mask bias during fill
    float* Pmax = Ms;                 // [64][2] partial row maxes (after fill)
    float* Rinv = Ms + 128;           // [64] 1/rowsum
    const uint32_t* Qu = (const uint32_t*)Qs;
    const uint32_t* Ku = (const uint32_t*)Kt;
    const uint32_t* Vu = (const uint32_t*)Vs;
    const uint32_t* Su = (const uint32_t*)S;

    int tid = threadIdx.x;
    int qt  = blockIdx.x;                 // 0..5
    int h   = blockIdx.y;                 // 0..3
    int i   = blockIdx.z;                 // 0..383
    size_t base = (size_t)i * JDIM;
    int col0 = h * HDIM;
    int qbase = qt * QT;

    // ---- stage 0: mask bias into smem ----
    for (int k = tid; k < 384; k += 256)
        Ms[k] = 1e9f * (mask[base + k] - 1.0f);
    __syncthreads();

    // ---- stage 1: fills (all tf32 bits already; no cvt) ----
    {
        int q  = tid >> 2;
        int d4 = (tid & 3) << 2;
#pragma unroll
        for (int half = 0; half < 2; half++) {
            *(float4*)(Qs + q * 36 + d4 + 16*half) =
                *(const float4*)(g_q + (base + qbase + q) * CDIM + col0 + d4 + 16*half);
        }
    }
#pragma unroll
    for (int it = 0; it < 12; it++) {
        int idx = it * 256 + tid;
        int k  = idx >> 3;
        int d4 = (idx & 7) << 2;
        float4 v = *(const float4*)(g_k + (base + k) * CDIM + col0 + d4);
        Kt[(d4+0)*392 + k] = v.x;
        Kt[(d4+1)*392 + k] = v.y;
        Kt[(d4+2)*392 + k] = v.z;
        Kt[(d4+3)*392 + k] = v.w;
        *(float4*)(Vs + k * 40 + d4) =
            *(const float4*)(g_v + (base + k) * CDIM + col0 + d4);
    }
    // S init = tri-bias + mask bias
    {
        const float* tbh = g_tb + (size_t)h * NTOK + (size_t)qbase * JDIM;
#pragma unroll
        for (int it = 0; it < 24; it++) {
            int idx = it * 256 + tid;
            int q  = idx / 96;
            int c4 = (idx - q * 96) << 2;
            float4 tb = *(const float4*)(tbh + q * JDIM + c4);
            float4 mm = *(const float4*)(Ms + c4);
            float4 o;
            o.x = tb.x + mm.x; o.y = tb.y + mm.y;
            o.z = tb.z + mm.z; o.w = tb.w + mm.w;
            *(float4*)(S + q * 388 + c4) = o;
        }
    }
    __syncthreads();

    int w    = tid >> 5;
    int lane = tid & 31;
    int gr   = lane >> 2;   // 0..7
    int tg   = lane & 3;    // 0..3

    // ================= QK^T (epilogue: RMW S, track row max) =========
    {
        int m0 = (w & 3) * 16;
        int nh = (w >> 2) * 192;
        float mA = -1e30f, mB = -1e30f;

#pragma unroll 1
        for (int ng = 0; ng < 3; ng++) {
            int nc = nh + ng * 64;
            float acc[8][4];
#pragma unroll
            for (int t = 0; t < 8; t++)
#pragma unroll
                for (int e = 0; e < 4; e++) acc[t][e] = 0.0f;

#pragma unroll
            for (int ks = 0; ks < 4; ks++) {
                int k0 = ks * 8;
                uint32_t a0 = Qu[(m0+gr)   * 36 + k0 + tg];
                uint32_t a1 = Qu[(m0+gr+8) * 36 + k0 + tg];
                uint32_t a2 = Qu[(m0+gr)   * 36 + k0 + tg + 4];
                uint32_t a3 = Qu[(m0+gr+8) * 36 + k0 + tg + 4];
#pragma unroll
                for (int t = 0; t < 8; t++) {
                    int n0 = nc + t * 8;
                    uint32_t b0 = Ku[(k0+tg)   * 392 + n0 + gr];
                    uint32_t b1 = Ku[(k0+tg+4) * 392 + n0 + gr];
                    mma_tf32(acc[t], a0, a1, a2, a3, b0, b1);
                }
            }
#pragma unroll
            for (int t = 0; t < 8; t++) {
                int col = nc + t * 8 + tg * 2;
                float* p0 = S + (m0+gr)   * 388 + col;
                float* p1 = S + (m0+gr+8) * 388 + col;
                float2 s0 = *(float2*)p0;
                float2 s1 = *(float2*)p1;
                s0.x += acc[t][0]; s0.y += acc[t][1];
                s1.x += acc[t][2]; s1.y += acc[t][3];
                mA = fmaxf(mA, fmaxf(s0.x, s0.y));
                mB = fmaxf(mB, fmaxf(s1.x, s1.y));
                *(float2*)p0 = s0;
                *(float2*)p1 = s1;
            }
        }
        // quad-reduce maxes (lanes gr*4+tg share gr)
        mA = fmaxf(mA, __shfl_xor_sync(0xffffffffu, mA, 1));
        mA = fmaxf(mA, __shfl_xor_sync(0xffffffffu, mA, 2));
        mB = fmaxf(mB, __shfl_xor_sync(0xffffffffu, mB, 1));
        mB = fmaxf(mB, __shfl_xor_sync(0xffffffffu, mB, 2));
        if (tg == 0) {
            Pmax[(m0+gr)   * 2 + (w >> 2)] = mA;
            Pmax[(m0+gr+8) * 2 + (w >> 2)] = mB;
        }
    }
    __syncthreads();

    // ============ exp pass (unnormalized, tf32 out) + row sums =======
    {
        int row = tid >> 2;
        int c0  = (tid & 3) * 2;
        float* srow = S + row * 388;
        float mx = fmaxf(Pmax[row*2], Pmax[row*2+1]);
        float sum = 0.0f;
#pragma unroll
        for (int t = 0; t < 48; t++) {
            float2 v = *(const float2*)(srow + c0 + 8*t);
            v.x = __expf(v.x - mx);
            v.y = __expf(v.y - mx);
            sum += v.x + v.y;
            v.x = __uint_as_float(f2tf(v.x));
            v.y = __uint_as_float(f2tf(v.y));
            *(float2*)(srow + c0 + 8*t) = v;
        }
        sum += __shfl_xor_sync(0xffffffffu, sum, 1);
        sum += __shfl_xor_sync(0xffffffffu, sum, 2);
        if ((tid & 3) == 0) Rinv[row] = 1.0f / sum;
    }
    __syncthreads();

    // ================= O = P V (scale by Rinv, gate, store) ==========
    {
        int m0 = (w & 3) * 16;
        int d0 = (w >> 2) * 16;
        float acc[2][4];
#pragma unroll
        for (int t = 0; t < 2; t++)
#pragma unroll
            for (int e = 0; e < 4; e++) acc[t][e] = 0.0f;

#pragma unroll 4
        for (int ks = 0; ks < 48; ks++) {
            int k0 = ks * 8;
            uint32_t a0 = Su[(m0+gr)   * 388 + k0 + tg];
            uint32_t a1 = Su[(m0+gr+8) * 388 + k0 + tg];
            uint32_t a2 = Su[(m0+gr)   * 388 + k0 + tg + 4];
            uint32_t a3 = Su[(m0+gr+8) * 388 + k0 + tg + 4];
#pragma unroll
            for (int t = 0; t < 2; t++) {
                int n0 = d0 + t * 8;
                uint32_t b0 = Vu[(k0+tg)   * 40 + n0 + gr];
                uint32_t b1 = Vu[(k0+tg+4) * 40 + n0 + gr];
                mma_tf32(acc[t], a0, a1, a2, a3, b0, b1);
            }
        }

        float inv0 = Rinv[m0+gr];
        float inv1 = Rinv[m0+gr+8];
        size_t tok0 = base + qbase + m0 + gr;
        size_t tok1 = tok0 + 8;
#pragma unroll
        for (int t = 0; t < 2; t++) {
            int col = col0 + d0 + t * 8 + tg * 2;
            float2 gA = *(const float2*)(g_gt + tok0 * CDIM + col);
            float2 gB = *(const float2*)(g_gt + tok1 * CDIM + col);
            float2 o0, o1;
            o0.x = __uint_as_float(f2tf(acc[t][0] * inv0 * gA.x));
            o0.y = __uint_as_float(f2tf(acc[t][1] * inv0 * gA.y));
            o1.x = __uint_as_float(f2tf(acc[t][2] * inv1 * gB.x));
            o1.y = __uint_as_float(f2tf(acc[t][3] * inv1 * gB.y));
            *(float2*)(g_og + tok0 * CDIM + col) = o0;
            *(float2*)(g_og + tok1 * CDIM + col) = o1;
        }
    }
}

// =====================================================================
// launch
// =====================================================================
extern "C" void kernel_launch(void* const* d_in, const int* in_sizes, int n_in,
                              void* d_out, int out_size)
{
    const float* x    = (const float*)d_in[0];
    const float* mask = (const float*)d_in[1];
    const float* lnw  = (const float*)d_in[2];
    const float* lnb  = (const float*)d_in[3];
    const float* wz   = (const float*)d_in[4];
    const float* bz   = (const float*)d_in[5];
    const float* wq   = (const float*)d_in[6];
    const float* wk   = (const float*)d_in[7];
    const float* wv   = (const float*)d_in[8];
    const float* wg   = (const float*)d_in[9];
    const float* bg   = (const float*)d_in[10];
    const float* wo   = (const float*)d_in[11];
    const float* bo   = (const float*)d_in[12];
    float* out = (float*)d_out;

    float *p_xln, *p_og;
    cudaGetSymbolAddress((void**)&p_xln, g_xln);
    cudaGetSymbolAddress((void**)&p_og,  g_og);

    cudaFuncSetAttribute(proj4_tc, cudaFuncAttributeMaxDynamicSharedMemorySize,
                         PJ_SMEM_BYTES);
    cudaFuncSetAttribute(gemm_out_tc, cudaFuncAttributeMaxDynamicSharedMemorySize,
                         PJ_SMEM_BYTES);
    cudaFuncSetAttribute(attn_mma_kernel, cudaFuncAttributeMaxDynamicSharedMemorySize,
                         AT_SMEM_BYTES);

    // 0) weight conversion (tf32)
    wconv_kernel<<<320, 256>>>(wq, wk, wv, wg, wo);

    // 1) LayerNorm + tri-bias
    ln_z_kernel<<<NTOK / 8, 256>>>(x, lnw, lnb, wz, bz);

    // 2) fused projections q/k/v/gate (tensor)
    proj4_tc<<<NTOK / 64, 128, PJ_SMEM_BYTES>>>(p_xln, bg);

    // 3) attention on mma.sync tf32, gate fused
    attn_mma_kernel<<<dim3(6, HEADS, IDIM), 256, AT_SMEM_BYTES>>>(mask);

    // 4) output projection (tensor)
    gemm_out_tc<<<NTOK / 64, 128, PJ_SMEM_BYTES>>>(p_og, bo, out);
}

// round 6
// speedup vs baseline: 2.8945x; 1.2626x over previous
#include <cuda_runtime.h>
#include <math.h>
#include <stdint.h>

// Problem constants
#define IDIM   384
#define JDIM   384
#define NTOK   (IDIM*JDIM)      // 147456
#define CDIM   128
#define HEADS  4
#define HDIM   32
#define QSCALE 0.17677669529663687f   // 1/sqrt(32)

// -------- scratch (device globals; no allocation allowed) --------
__device__ float g_xln[(size_t)NTOK*CDIM];   // tf32 bits
__device__ float g_q  [(size_t)NTOK*CDIM];   // tf32 bits (scaled)
__device__ float g_k  [(size_t)NTOK*CDIM];   // tf32 bits
__device__ float g_v  [(size_t)NTOK*CDIM];   // tf32 bits
__device__ float g_gt [(size_t)NTOK*CDIM];   // fp32 sigmoid gate
__device__ float g_og [(size_t)NTOK*CDIM];   // tf32 bits (o * gate)
__device__ float g_tb [(size_t)HEADS*NTOK];  // fp32 [h][q*384+k]
__device__ float g_wt [4*16384];             // tf32 bits wq,wk,wv,wg
__device__ float g_wot[16384];               // tf32 bits wo

// ---------- tf32 mma.sync helpers ----------
__device__ __forceinline__ uint32_t f2tf(float x) {
    uint32_t r;
    asm("cvt.rna.tf32.f32 %0, %1;" : "=r"(r) : "f"(x));
    return r;
}
__device__ __forceinline__ void mma_tf32(float* d,
                                         uint32_t a0, uint32_t a1,
                                         uint32_t a2, uint32_t a3,
                                         uint32_t b0, uint32_t b1) {
    asm volatile(
        "mma.sync.aligned.m16n8k8.row.col.f32.tf32.tf32.f32 "
        "{%0,%1,%2,%3}, {%4,%5,%6,%7}, {%8,%9}, {%0,%1,%2,%3};"
        : "+f"(d[0]), "+f"(d[1]), "+f"(d[2]), "+f"(d[3])
        : "r"(a0), "r"(a1), "r"(a2), "r"(a3), "r"(b0), "r"(b1));
}

// =====================================================================
// Kernel 0: convert weights to tf32 (one-shot, tiny)
// =====================================================================
__global__ __launch_bounds__(256) void wconv_kernel(
    const float* __restrict__ wq, const float* __restrict__ wk,
    const float* __restrict__ wv, const float* __restrict__ wg,
    const float* __restrict__ wo)
{
    int idx = blockIdx.x * 256 + threadIdx.x;   // < 81920
    int w   = idx >> 14;
    int off = idx & 16383;
    const float* src = (w == 0) ? wq : (w == 1) ? wk : (w == 2) ? wv
                     : (w == 3) ? wg : wo;
    float v = src[off];
    float t = __uint_as_float(f2tf(v));
    if (w < 4) g_wt[idx] = t;
    else       g_wot[off] = t;
}

// =====================================================================
// Kernel 1: LayerNorm (tf32 output) + tri-bias projection (fp32)
// =====================================================================
__global__ __launch_bounds__(256) void ln_z_kernel(
    const float* __restrict__ x,
    const float* __restrict__ lnw, const float* __restrict__ lnb,
    const float* __restrict__ wz,  const float* __restrict__ bz)
{
    int warp = threadIdx.x >> 5;
    int lane = threadIdx.x & 31;
    size_t token = (size_t)blockIdx.x * 8 + warp;

    float4 xv = ((const float4*)(x + token * CDIM))[lane];

    float s = xv.x + xv.y + xv.z + xv.w;
#pragma unroll
    for (int m = 16; m; m >>= 1) s += __shfl_xor_sync(0xffffffffu, s, m);
    float mu = s * (1.0f / 128.0f);

    float dx = xv.x - mu, dy = xv.y - mu, dz = xv.z - mu, dw = xv.w - mu;
    float s2 = dx*dx + dy*dy + dz*dz + dw*dw;
#pragma unroll
    for (int m = 16; m; m >>= 1) s2 += __shfl_xor_sync(0xffffffffu, s2, m);
    float rstd = rsqrtf(s2 * (1.0f / 128.0f) + 1e-5f);

    float4 wv = ((const float4*)lnw)[lane];
    float4 bv = ((const float4*)lnb)[lane];
    float4 y;
    y.x = dx * rstd * wv.x + bv.x;
    y.y = dy * rstd * wv.y + bv.y;
    y.z = dz * rstd * wv.z + bv.z;
    y.w = dw * rstd * wv.w + bv.w;

    // tri-bias in fp32
    const float4* wzr = (const float4*)wz;
    int c = lane * 4;
    float4 w0 = wzr[c], w1 = wzr[c+1], w2 = wzr[c+2], w3 = wzr[c+3];
    float4 a;
    a.x = y.x*w0.x + y.y*w1.x + y.z*w2.x + y.w*w3.x;
    a.y = y.x*w0.y + y.y*w1.y + y.z*w2.y + y.w*w3.y;
    a.z = y.x*w0.z + y.y*w1.z + y.z*w2.z + y.w*w3.z;
    a.w = y.x*w0.w + y.y*w1.w + y.z*w2.w + y.w*w3.w;
#pragma unroll
    for (int m = 16; m; m >>= 1) {
        a.x += __shfl_xor_sync(0xffffffffu, a.x, m);
        a.y += __shfl_xor_sync(0xffffffffu, a.y, m);
        a.z += __shfl_xor_sync(0xffffffffu, a.z, m);
        a.w += __shfl_xor_sync(0xffffffffu, a.w, m);
    }
    if (lane == 0) {
        g_tb[0*(size_t)NTOK + token] = a.x + bz[0];
        g_tb[1*(size_t)NTOK + token] = a.y + bz[1];
        g_tb[2*(size_t)NTOK + token] = a.z + bz[2];
        g_tb[3*(size_t)NTOK + token] = a.w + bz[3];
    }

    // store x_ln as tf32 bits
    float4 yt;
    yt.x = __uint_as_float(f2tf(y.x));
    yt.y = __uint_as_float(f2tf(y.y));
    yt.z = __uint_as_float(f2tf(y.z));
    yt.w = __uint_as_float(f2tf(y.w));
    ((float4*)(g_xln + token * CDIM))[lane] = yt;
}

// =====================================================================
// Tensor-core projection kernels (mma.sync tf32)
// CTA: 64 rows x 128 cols, 128 threads / 4 warps, warp tile 32x64
// =====================================================================
#define PJ_LD 132
#define PJ_SMEM_BYTES ((64*PJ_LD + 128*PJ_LD)*4)   // 101376

__device__ __forceinline__ void pj_compute(
    const uint32_t* Au, const uint32_t* Bu,
    int m0, int nb, int gr, int tg, float acc[2][8][4])
{
#pragma unroll
    for (int im = 0; im < 2; im++)
#pragma unroll
        for (int t = 0; t < 8; t++)
#pragma unroll
            for (int e = 0; e < 4; e++) acc[im][t][e] = 0.0f;

#pragma unroll 4
    for (int ks = 0; ks < 16; ks++) {
        int k0 = ks * 8;
        uint32_t a[2][4];
#pragma unroll
        for (int im = 0; im < 2; im++) {
            int mb = m0 + im * 16;
            a[im][0] = Au[(mb+gr)   * PJ_LD + k0 + tg];
            a[im][1] = Au[(mb+gr+8) * PJ_LD + k0 + tg];
            a[im][2] = Au[(mb+gr)   * PJ_LD + k0 + tg + 4];
            a[im][3] = Au[(mb+gr+8) * PJ_LD + k0 + tg + 4];
        }
#pragma unroll
        for (int t = 0; t < 8; t++) {
            int n0 = nb + t * 8;
            uint32_t b0 = Bu[(k0+tg)   * PJ_LD + n0 + gr];
            uint32_t b1 = Bu[(k0+tg+4) * PJ_LD + n0 + gr];
            mma_tf32(acc[0][t], a[0][0], a[0][1], a[0][2], a[0][3], b0, b1);
            mma_tf32(acc[1][t], a[1][0], a[1][1], a[1][2], a[1][3], b0, b1);
        }
    }
}

__global__ __launch_bounds__(128) void proj4_tc(
    const float* __restrict__ A, const float* __restrict__ bg)
{
    extern __shared__ float sm[];
    float* As = sm;                 // [64][132]
    float* Bs = sm + 64 * PJ_LD;    // [128][132]
    const uint32_t* Au = (const uint32_t*)As;
    const uint32_t* Bu = (const uint32_t*)Bs;

    int tid = threadIdx.x;
    size_t rowbase = (size_t)blockIdx.x * 64;

#pragma unroll
    for (int it = 0; it < 16; it++) {
        int idx = it * 128 + tid;
        int m  = idx >> 5;
        int c4 = (idx & 31) << 2;
        *(float4*)(As + m * PJ_LD + c4) =
            *(const float4*)(A + (rowbase + m) * CDIM + c4);
    }

    int w = tid >> 5, lane = tid & 31;
    int gr = lane >> 2, tg = lane & 3;
    int m0 = (w & 1) * 32;
    int nb = (w >> 1) * 64;

    float* outs[4] = {g_q, g_k, g_v, g_gt};

#pragma unroll 1
    for (int wi = 0; wi < 4; wi++) {
        __syncthreads();
#pragma unroll
        for (int it = 0; it < 32; it++) {
            int idx = it * 128 + tid;
            int k  = idx >> 5;
            int n4 = (idx & 31) << 2;
            *(float4*)(Bs + k * PJ_LD + n4) =
                *(const float4*)(g_wt + wi * 16384 + k * 128 + n4);
        }
        __syncthreads();

        float acc[2][8][4];
        pj_compute(Au, Bu, m0, nb, gr, tg, acc);

        float* out = outs[wi];
#pragma unroll
        for (int im = 0; im < 2; im++) {
            size_t r0 = rowbase + m0 + im * 16 + gr;
            size_t r1 = r0 + 8;
#pragma unroll
            for (int t = 0; t < 8; t++) {
                int col = nb + t * 8 + tg * 2;
                float2 v0 = make_float2(acc[im][t][0], acc[im][t][1]);
                float2 v1 = make_float2(acc[im][t][2], acc[im][t][3]);
                if (wi == 0) {
                    v0.x = __uint_as_float(f2tf(v0.x * QSCALE));
                    v0.y = __uint_as_float(f2tf(v0.y * QSCALE));
                    v1.x = __uint_as_float(f2tf(v1.x * QSCALE));
                    v1.y = __uint_as_float(f2tf(v1.y * QSCALE));
                } else if (wi < 3) {
                    v0.x = __uint_as_float(f2tf(v0.x));
                    v0.y = __uint_as_float(f2tf(v0.y));
                    v1.x = __uint_as_float(f2tf(v1.x));
                    v1.y = __uint_as_float(f2tf(v1.y));
                } else {
                    float2 b = *(const float2*)(bg + col);
                    v0.x = 1.0f / (1.0f + __expf(-(v0.x + b.x)));
                    v0.y = 1.0f / (1.0f + __expf(-(v0.y + b.y)));
                    v1.x = 1.0f / (1.0f + __expf(-(v1.x + b.x)));
                    v1.y = 1.0f / (1.0f + __expf(-(v1.y + b.y)));
                }
                *(float2*)(out + r0 * CDIM + col) = v0;
                *(float2*)(out + r1 * CDIM + col) = v1;
            }
        }
    }
}

__global__ __launch_bounds__(128) void gemm_out_tc(
    const float* __restrict__ A, const float* __restrict__ bias,
    float* __restrict__ out)
{
    extern __shared__ float sm[];
    float* As = sm;
    float* Bs = sm + 64 * PJ_LD;
    const uint32_t* Au = (const uint32_t*)As;
    const uint32_t* Bu = (const uint32_t*)Bs;

    int tid = threadIdx.x;
    size_t rowbase = (size_t)blockIdx.x * 64;

#pragma unroll
    for (int it = 0; it < 16; it++) {
        int idx = it * 128 + tid;
        int m  = idx >> 5;
        int c4 = (idx & 31) << 2;
        *(float4*)(As + m * PJ_LD + c4) =
            *(const float4*)(A + (rowbase + m) * CDIM + c4);
    }
#pragma unroll
    for (int it = 0; it < 32; it++) {
        int idx = it * 128 + tid;
        int k  = idx >> 5;
        int n4 = (idx & 31) << 2;
        *(float4*)(Bs + k * PJ_LD + n4) =
            *(const float4*)(g_wot + k * 128 + n4);
    }
    __syncthreads();

    int w = tid >> 5, lane = tid & 31;
    int gr = lane >> 2, tg = lane & 3;
    int m0 = (w & 1) * 32;
    int nb = (w >> 1) * 64;

    float acc[2][8][4];
    pj_compute(Au, Bu, m0, nb, gr, tg, acc);

#pragma unroll
    for (int im = 0; im < 2; im++) {
        size_t r0 = rowbase + m0 + im * 16 + gr;
        size_t r1 = r0 + 8;
#pragma unroll
        for (int t = 0; t < 8; t++) {
            int col = nb + t * 8 + tg * 2;
            float2 b = *(const float2*)(bias + col);
            float2 v0 = make_float2(acc[im][t][0] + b.x, acc[im][t][1] + b.y);
            float2 v1 = make_float2(acc[im][t][2] + b.x, acc[im][t][3] + b.y);
            *(float2*)(out + r0 * CDIM + col) = v0;
            *(float2*)(out + r1 * CDIM + col) = v1;
        }
    }
}

// =====================================================================
// Kernel 3: flash-style tf32 mma.sync attention, online softmax
//   CTA per (qtile=64, head, i). 256 threads / 8 warps.
//   k processed in 3 blocks of 128; S lives in registers.
// smem (floats):
//   Qs  [64][36]    2304
//   Kt  [32][137]   4384  (transposed K block, stride 137 conflict-free)
//   Vs  [128][40]   5120
//   P   [64][132]   8448  (unnormalized exp, tf32 bits)
//   Ms  [384]       mask bias
//   Pmax[64][2], Psum[64][2]
// total 20896 floats = 83584 B -> 2 CTAs/SM
// =====================================================================
#define KBS 128
#define KT_LD 137
#define P_LD  132
#define OFF_KT   2304
#define OFF_VS   (OFF_KT + 32*KT_LD)          // 6688
#define OFF_P    (OFF_VS + KBS*40)            // 11808
#define OFF_MS   (OFF_P + 64*P_LD)            // 20256
#define OFF_PMAX (OFF_MS + 384)               // 20640
#define OFF_PSUM (OFF_PMAX + 128)             // 20768
#define AT_SMEM_FLOATS (OFF_PSUM + 128)       // 20896
#define AT_SMEM_BYTES  (AT_SMEM_FLOATS*4)     // 83584

__global__ __launch_bounds__(256, 2) void attn_flash(const float* __restrict__ mask)
{
    extern __shared__ float sm[];
    float* Qs   = sm;
    float* Kt   = sm + OFF_KT;
    float* Vs   = sm + OFF_VS;
    float* P    = sm + OFF_P;
    float* Ms   = sm + OFF_MS;
    float* Pmax = sm + OFF_PMAX;
    float* Psum = sm + OFF_PSUM;
    const uint32_t* Qu = (const uint32_t*)Qs;
    const uint32_t* Ku = (const uint32_t*)Kt;
    const uint32_t* Vu = (const uint32_t*)Vs;
    const uint32_t* Pu = (const uint32_t*)P;

    int tid = threadIdx.x;
    int qt  = blockIdx.x;                 // 0..5
    int h   = blockIdx.y;                 // 0..3
    int i   = blockIdx.z;                 // 0..383
    size_t base = (size_t)i * JDIM;
    int col0 = h * HDIM;
    int qbase = qt * 64;

    // ---- mask bias + Q fill ----
    for (int k = tid; k < 384; k += 256)
        Ms[k] = 1e9f * (mask[base + k] - 1.0f);
    {
        int q  = tid >> 2;
        int d4 = (tid & 3) << 2;
#pragma unroll
        for (int half = 0; half < 2; half++) {
            *(float4*)(Qs + q * 36 + d4 + 16*half) =
                *(const float4*)(g_q + (base + qbase + q) * CDIM + col0 + d4 + 16*half);
        }
    }
    __syncthreads();

    int w    = tid >> 5;
    int lane = tid & 31;
    int gr   = lane >> 2;   // 0..7
    int tg   = lane & 3;    // 0..3
    int m0   = (w & 3) * 16;
    int half = w >> 2;      // 0..1
    int nh   = half * 64;   // QK n-offset within k-block
    int d0   = half * 16;   // PV d-offset

    // hoist Q fragments (reused all blocks)
    uint32_t aq[4][4];
#pragma unroll
    for (int ks = 0; ks < 4; ks++) {
        int k0 = ks * 8;
        aq[ks][0] = Qu[(m0+gr)   * 36 + k0 + tg];
        aq[ks][1] = Qu[(m0+gr+8) * 36 + k0 + tg];
        aq[ks][2] = Qu[(m0+gr)   * 36 + k0 + tg + 4];
        aq[ks][3] = Qu[(m0+gr+8) * 36 + k0 + tg + 4];
    }

    const float* tb0 = g_tb + (size_t)h * NTOK + (size_t)(qbase + m0 + gr) * JDIM;
    const float* tb1 = tb0 + 8 * JDIM;

    float oacc[2][4];
#pragma unroll
    for (int t = 0; t < 2; t++)
#pragma unroll
        for (int e = 0; e < 4; e++) oacc[t][e] = 0.0f;
    float mrun0 = -1e30f, mrun1 = -1e30f;
    float l0 = 0.0f, l1 = 0.0f;

    int r0 = m0 + gr, r1 = r0 + 8;

#pragma unroll 1
    for (int kb = 0; kb < 3; kb++) {
        __syncthreads();   // prior PV / Pmax reads done before refill
        // ---- fill Kt (transposed) and Vs for this k-block ----
#pragma unroll
        for (int it = 0; it < 4; it++) {
            int idx = it * 256 + tid;
            int k  = idx >> 3;
            int d4 = (idx & 7) << 2;
            size_t grow = (base + kb * KBS + k) * CDIM + col0 + d4;
            float4 kv = *(const float4*)(g_k + grow);
            Kt[(d4+0)*KT_LD + k] = kv.x;
            Kt[(d4+1)*KT_LD + k] = kv.y;
            Kt[(d4+2)*KT_LD + k] = kv.z;
            Kt[(d4+3)*KT_LD + k] = kv.w;
            *(float4*)(Vs + k * 40 + d4) = *(const float4*)(g_v + grow);
        }
        __syncthreads();

        // ---- QK^T into registers ----
        float sacc[8][4];
#pragma unroll
        for (int t = 0; t < 8; t++)
#pragma unroll
            for (int e = 0; e < 4; e++) sacc[t][e] = 0.0f;

#pragma unroll
        for (int ks = 0; ks < 4; ks++) {
            int k0 = ks * 8;
#pragma unroll
            for (int t = 0; t < 8; t++) {
                int n0 = nh + t * 8;
                uint32_t b0 = Ku[(k0+tg)   * KT_LD + n0 + gr];
                uint32_t b1 = Ku[(k0+tg+4) * KT_LD + n0 + gr];
                mma_tf32(sacc[t], aq[ks][0], aq[ks][1], aq[ks][2], aq[ks][3], b0, b1);
            }
        }

        // ---- add biases, block row max ----
        float mA = -1e30f, mB = -1e30f;
        int kgbase = kb * KBS + nh;
#pragma unroll
        for (int t = 0; t < 8; t++) {
            int col = kgbase + t * 8 + tg * 2;
            float2 tA = *(const float2*)(tb0 + col);
            float2 tB = *(const float2*)(tb1 + col);
            float2 mm = *(const float2*)(Ms + col);
            sacc[t][0] += tA.x + mm.x;  sacc[t][1] += tA.y + mm.y;
            sacc[t][2] += tB.x + mm.x;  sacc[t][3] += tB.y + mm.y;
            mA = fmaxf(mA, fmaxf(sacc[t][0], sacc[t][1]));
            mB = fmaxf(mB, fmaxf(sacc[t][2], sacc[t][3]));
        }
        mA = fmaxf(mA, __shfl_xor_sync(0xffffffffu, mA, 1));
        mA = fmaxf(mA, __shfl_xor_sync(0xffffffffu, mA, 2));
        mB = fmaxf(mB, __shfl_xor_sync(0xffffffffu, mB, 1));
        mB = fmaxf(mB, __shfl_xor_sync(0xffffffffu, mB, 2));
        if (tg == 0) {
            Pmax[r0 * 2 + half] = mA;
            Pmax[r1 * 2 + half] = mB;
        }
        __syncthreads();

        // ---- online max update ----
        float bm0 = fmaxf(Pmax[r0*2], Pmax[r0*2+1]);
        float bm1 = fmaxf(Pmax[r1*2], Pmax[r1*2+1]);
        float mn0 = fmaxf(mrun0, bm0);
        float mn1 = fmaxf(mrun1, bm1);
        float f0 = __expf(mrun0 - mn0);
        float f1 = __expf(mrun1 - mn1);
        mrun0 = mn0; mrun1 = mn1;

        // ---- exp (unnormalized) -> P smem (tf32), partial row sums ----
        float s0 = 0.0f, s1 = 0.0f;
#pragma unroll
        for (int t = 0; t < 8; t++) {
            int coll = nh + t * 8 + tg * 2;
            float2 p0, p1;
            p0.x = __expf(sacc[t][0] - mn0);
            p0.y = __expf(sacc[t][1] - mn0);
            p1.x = __expf(sacc[t][2] - mn1);
            p1.y = __expf(sacc[t][3] - mn1);
            s0 += p0.x + p0.y;
            s1 += p1.x + p1.y;
            p0.x = __uint_as_float(f2tf(p0.x));
            p0.y = __uint_as_float(f2tf(p0.y));
            p1.x = __uint_as_float(f2tf(p1.x));
            p1.y = __uint_as_float(f2tf(p1.y));
            *(float2*)(P + r0 * P_LD + coll) = p0;
            *(float2*)(P + r1 * P_LD + coll) = p1;
        }
        s0 += __shfl_xor_sync(0xffffffffu, s0, 1);
        s0 += __shfl_xor_sync(0xffffffffu, s0, 2);
        s1 += __shfl_xor_sync(0xffffffffu, s1, 1);
        s1 += __shfl_xor_sync(0xffffffffu, s1, 2);
        if (tg == 0) {
            Psum[r0 * 2 + half] = s0;
            Psum[r1 * 2 + half] = s1;
        }
        __syncthreads();

        // ---- rescale running state & accumulate PV ----
        l0 = l0 * f0 + Psum[r0*2] + Psum[r0*2+1];
        l1 = l1 * f1 + Psum[r1*2] + Psum[r1*2+1];
#pragma unroll
        for (int t = 0; t < 2; t++) {
            oacc[t][0] *= f0;  oacc[t][1] *= f0;
            oacc[t][2] *= f1;  oacc[t][3] *= f1;
        }
#pragma unroll 4
        for (int ks = 0; ks < 16; ks++) {
            int k0 = ks * 8;
            uint32_t a0 = Pu[r0 * P_LD + k0 + tg];
            uint32_t a1 = Pu[r1 * P_LD + k0 + tg];
            uint32_t a2 = Pu[r0 * P_LD + k0 + tg + 4];
            uint32_t a3 = Pu[r1 * P_LD + k0 + tg + 4];
#pragma unroll
            for (int t = 0; t < 2; t++) {
                int n0 = d0 + t * 8;
                uint32_t b0 = Vu[(k0+tg)   * 40 + n0 + gr];
                uint32_t b1 = Vu[(k0+tg+4) * 40 + n0 + gr];
                mma_tf32(oacc[t], a0, a1, a2, a3, b0, b1);
            }
        }
    }

    // ---- epilogue: O * (1/l) * gate -> g_og (tf32) ----
    {
        float inv0 = 1.0f / l0;
        float inv1 = 1.0f / l1;
        size_t tok0 = base + qbase + r0;
        size_t tok1 = base + qbase + r1;
#pragma unroll
        for (int t = 0; t < 2; t++) {
            int col = col0 + d0 + t * 8 + tg * 2;
            float2 gA = *(const float2*)(g_gt + tok0 * CDIM + col);
            float2 gB = *(const float2*)(g_gt + tok1 * CDIM + col);
            float2 o0, o1;
            o0.x = __uint_as_float(f2tf(oacc[t][0] * inv0 * gA.x));
            o0.y = __uint_as_float(f2tf(oacc[t][1] * inv0 * gA.y));
            o1.x = __uint_as_float(f2tf(oacc[t][2] * inv1 * gB.x));
            o1.y = __uint_as_float(f2tf(oacc[t][3] * inv1 * gB.y));
            *(float2*)(g_og + tok0 * CDIM + col) = o0;
            *(float2*)(g_og + tok1 * CDIM + col) = o1;
        }
    }
}

// =====================================================================
// launch
// =====================================================================
extern "C" void kernel_launch(void* const* d_in, const int* in_sizes, int n_in,
                              void* d_out, int out_size)
{
    const float* x    = (const float*)d_in[0];
    const float* mask = (const float*)d_in[1];
    const float* lnw  = (const float*)d_in[2];
    const float* lnb  = (const float*)d_in[3];
    const float* wz   = (const float*)d_in[4];
    const float* bz   = (const float*)d_in[5];
    const float* wq   = (const float*)d_in[6];
    const float* wk   = (const float*)d_in[7];
    const float* wv   = (const float*)d_in[8];
    const float* wg   = (const float*)d_in[9];
    const float* bg   = (const float*)d_in[10];
    const float* wo   = (const float*)d_in[11];
    const float* bo   = (const float*)d_in[12];
    float* out = (float*)d_out;

    float *p_xln, *p_og;
    cudaGetSymbolAddress((void**)&p_xln, g_xln);
    cudaGetSymbolAddress((void**)&p_og,  g_og);

    cudaFuncSetAttribute(proj4_tc, cudaFuncAttributeMaxDynamicSharedMemorySize,
                         PJ_SMEM_BYTES);
    cudaFuncSetAttribute(gemm_out_tc, cudaFuncAttributeMaxDynamicSharedMemorySize,
                         PJ_SMEM_BYTES);
    cudaFuncSetAttribute(attn_flash, cudaFuncAttributeMaxDynamicSharedMemorySize,
                         AT_SMEM_BYTES);

    // 0) weight conversion (tf32)
    wconv_kernel<<<320, 256>>>(wq, wk, wv, wg, wo);

    // 1) LayerNorm + tri-bias
    ln_z_kernel<<<NTOK / 8, 256>>>(x, lnw, lnb, wz, bz);

    // 2) fused projections q/k/v/gate (tensor)
    proj4_tc<<<NTOK / 64, 128, PJ_SMEM_BYTES>>>(p_xln, bg);

    // 3) flash attention on mma.sync tf32, gate fused
    attn_flash<<<dim3(6, HEADS, IDIM), 256, AT_SMEM_BYTES>>>(mask);

    // 4) output projection (tensor)
    gemm_out_tc<<<NTOK / 64, 128, PJ_SMEM_BYTES>>>(p_og, bo, out);
}

// round 7
// speedup vs baseline: 2.9751x; 1.0278x over previous
#include <cuda_runtime.h>
#include <math.h>
#include <stdint.h>

// Problem constants
#define IDIM   384
#define JDIM   384
#define NTOK   (IDIM*JDIM)      // 147456
#define CDIM   128
#define HEADS  4
#define HDIM   32
#define QSCALE 0.17677669529663687f   // 1/sqrt(32)

// -------- scratch (device globals; no allocation allowed) --------
__device__ float g_xln[(size_t)NTOK*CDIM];   // tf32 bits
__device__ float g_q  [(size_t)NTOK*CDIM];   // tf32 bits (scaled)
__device__ float g_k  [(size_t)NTOK*CDIM];   // tf32 bits
__device__ float g_v  [(size_t)NTOK*CDIM];   // tf32 bits
__device__ float g_gt [(size_t)NTOK*CDIM];   // fp32 sigmoid gate
__device__ float g_og [(size_t)NTOK*CDIM];   // tf32 bits (o * gate)
__device__ float g_tb [(size_t)HEADS*NTOK];  // fp32 [h][q*384+k]
__device__ float g_wt [4*16384];             // tf32 bits wq,wk,wv,wg
__device__ float g_wot[16384];               // tf32 bits wo

// ---------- tf32 mma.sync helpers ----------
__device__ __forceinline__ uint32_t f2tf(float x) {
    uint32_t r;
    asm("cvt.rna.tf32.f32 %0, %1;" : "=r"(r) : "f"(x));
    return r;
}
__device__ __forceinline__ void mma_tf32(float* d,
                                         uint32_t a0, uint32_t a1,
                                         uint32_t a2, uint32_t a3,
                                         uint32_t b0, uint32_t b1) {
    asm volatile(
        "mma.sync.aligned.m16n8k8.row.col.f32.tf32.tf32.f32 "
        "{%0,%1,%2,%3}, {%4,%5,%6,%7}, {%8,%9}, {%0,%1,%2,%3};"
        : "+f"(d[0]), "+f"(d[1]), "+f"(d[2]), "+f"(d[3])
        : "r"(a0), "r"(a1), "r"(a2), "r"(a3), "r"(b0), "r"(b1));
}

// =====================================================================
// Kernel 0: convert weights to tf32 (one-shot, tiny)
// =====================================================================
__global__ __launch_bounds__(256) void wconv_kernel(
    const float* __restrict__ wq, const float* __restrict__ wk,
    const float* __restrict__ wv, const float* __restrict__ wg,
    const float* __restrict__ wo)
{
    int idx = blockIdx.x * 256 + threadIdx.x;   // < 81920
    int w   = idx >> 14;
    int off = idx & 16383;
    const float* src = (w == 0) ? wq : (w == 1) ? wk : (w == 2) ? wv
                     : (w == 3) ? wg : wo;
    float v = src[off];
    float t = __uint_as_float(f2tf(v));
    if (w < 4) g_wt[idx] = t;
    else       g_wot[off] = t;
}

// =====================================================================
// Kernel 1: LayerNorm (tf32 output) + tri-bias projection (fp32)
// =====================================================================
__global__ __launch_bounds__(256) void ln_z_kernel(
    const float* __restrict__ x,
    const float* __restrict__ lnw, const float* __restrict__ lnb,
    const float* __restrict__ wz,  const float* __restrict__ bz)
{
    int warp = threadIdx.x >> 5;
    int lane = threadIdx.x & 31;
    size_t token = (size_t)blockIdx.x * 8 + warp;

    float4 xv = ((const float4*)(x + token * CDIM))[lane];

    float s = xv.x + xv.y + xv.z + xv.w;
#pragma unroll
    for (int m = 16; m; m >>= 1) s += __shfl_xor_sync(0xffffffffu, s, m);
    float mu = s * (1.0f / 128.0f);

    float dx = xv.x - mu, dy = xv.y - mu, dz = xv.z - mu, dw = xv.w - mu;
    float s2 = dx*dx + dy*dy + dz*dz + dw*dw;
#pragma unroll
    for (int m = 16; m; m >>= 1) s2 += __shfl_xor_sync(0xffffffffu, s2, m);
    float rstd = rsqrtf(s2 * (1.0f / 128.0f) + 1e-5f);

    float4 wv = ((const float4*)lnw)[lane];
    float4 bv = ((const float4*)lnb)[lane];
    float4 y;
    y.x = dx * rstd * wv.x + bv.x;
    y.y = dy * rstd * wv.y + bv.y;
    y.z = dz * rstd * wv.z + bv.z;
    y.w = dw * rstd * wv.w + bv.w;

    const float4* wzr = (const float4*)wz;
    int c = lane * 4;
    float4 w0 = wzr[c], w1 = wzr[c+1], w2 = wzr[c+2], w3 = wzr[c+3];
    float4 a;
    a.x = y.x*w0.x + y.y*w1.x + y.z*w2.x + y.w*w3.x;
    a.y = y.x*w0.y + y.y*w1.y + y.z*w2.y + y.w*w3.y;
    a.z = y.x*w0.z + y.y*w1.z + y.z*w2.z + y.w*w3.z;
    a.w = y.x*w0.w + y.y*w1.w + y.z*w2.w + y.w*w3.w;
#pragma unroll
    for (int m = 16; m; m >>= 1) {
        a.x += __shfl_xor_sync(0xffffffffu, a.x, m);
        a.y += __shfl_xor_sync(0xffffffffu, a.y, m);
        a.z += __shfl_xor_sync(0xffffffffu, a.z, m);
        a.w += __shfl_xor_sync(0xffffffffu, a.w, m);
    }
    if (lane == 0) {
        g_tb[0*(size_t)NTOK + token] = a.x + bz[0];
        g_tb[1*(size_t)NTOK + token] = a.y + bz[1];
        g_tb[2*(size_t)NTOK + token] = a.z + bz[2];
        g_tb[3*(size_t)NTOK + token] = a.w + bz[3];
    }

    float4 yt;
    yt.x = __uint_as_float(f2tf(y.x));
    yt.y = __uint_as_float(f2tf(y.y));
    yt.z = __uint_as_float(f2tf(y.z));
    yt.w = __uint_as_float(f2tf(y.w));
    ((float4*)(g_xln + token * CDIM))[lane] = yt;
}

// =====================================================================
// Tensor-core projection kernels (mma.sync tf32)
// CTA: 64 rows x 128 cols, 128 threads / 4 warps, warp tile 32x64
// PJ_LD = 136 (== 8 mod 32): conflict-free A and B fragment loads
// =====================================================================
#define PJ_LD 136
#define PJ_SMEM_BYTES ((64*PJ_LD + 128*PJ_LD)*4)   // 104448

__device__ __forceinline__ void pj_compute(
    const uint32_t* Au, const uint32_t* Bu,
    int m0, int nb, int gr, int tg, float acc[2][8][4])
{
#pragma unroll
    for (int im = 0; im < 2; im++)
#pragma unroll
        for (int t = 0; t < 8; t++)
#pragma unroll
            for (int e = 0; e < 4; e++) acc[im][t][e] = 0.0f;

#pragma unroll 4
    for (int ks = 0; ks < 16; ks++) {
        int k0 = ks * 8;
        uint32_t a[2][4];
#pragma unroll
        for (int im = 0; im < 2; im++) {
            int mb = m0 + im * 16;
            a[im][0] = Au[(mb+gr)   * PJ_LD + k0 + tg];
            a[im][1] = Au[(mb+gr+8) * PJ_LD + k0 + tg];
            a[im][2] = Au[(mb+gr)   * PJ_LD + k0 + tg + 4];
            a[im][3] = Au[(mb+gr+8) * PJ_LD + k0 + tg + 4];
        }
#pragma unroll
        for (int t = 0; t < 8; t++) {
            int n0 = nb + t * 8;
            uint32_t b0 = Bu[(k0+tg)   * PJ_LD + n0 + gr];
            uint32_t b1 = Bu[(k0+tg+4) * PJ_LD + n0 + gr];
            mma_tf32(acc[0][t], a[0][0], a[0][1], a[0][2], a[0][3], b0, b1);
            mma_tf32(acc[1][t], a[1][0], a[1][1], a[1][2], a[1][3], b0, b1);
        }
    }
}

__global__ __launch_bounds__(128) void proj4_tc(
    const float* __restrict__ A, const float* __restrict__ bg)
{
    extern __shared__ float sm[];
    float* As = sm;                 // [64][136]
    float* Bs = sm + 64 * PJ_LD;    // [128][136]
    const uint32_t* Au = (const uint32_t*)As;
    const uint32_t* Bu = (const uint32_t*)Bs;

    int tid = threadIdx.x;
    size_t rowbase = (size_t)blockIdx.x * 64;

#pragma unroll
    for (int it = 0; it < 16; it++) {
        int idx = it * 128 + tid;
        int m  = idx >> 5;
        int c4 = (idx & 31) << 2;
        *(float4*)(As + m * PJ_LD + c4) =
            *(const float4*)(A + (rowbase + m) * CDIM + c4);
    }

    int w = tid >> 5, lane = tid & 31;
    int gr = lane >> 2, tg = lane & 3;
    int m0 = (w & 1) * 32;
    int nb = (w >> 1) * 64;

    float* outs[4] = {g_q, g_k, g_v, g_gt};

#pragma unroll 1
    for (int wi = 0; wi < 4; wi++) {
        __syncthreads();
#pragma unroll
        for (int it = 0; it < 32; it++) {
            int idx = it * 128 + tid;
            int k  = idx >> 5;
            int n4 = (idx & 31) << 2;
            *(float4*)(Bs + k * PJ_LD + n4) =
                *(const float4*)(g_wt + wi * 16384 + k * 128 + n4);
        }
        __syncthreads();

        float acc[2][8][4];
        pj_compute(Au, Bu, m0, nb, gr, tg, acc);

        float* out = outs[wi];
#pragma unroll
        for (int im = 0; im < 2; im++) {
            size_t r0 = rowbase + m0 + im * 16 + gr;
            size_t r1 = r0 + 8;
#pragma unroll
            for (int t = 0; t < 8; t++) {
                int col = nb + t * 8 + tg * 2;
                float2 v0 = make_float2(acc[im][t][0], acc[im][t][1]);
                float2 v1 = make_float2(acc[im][t][2], acc[im][t][3]);
                if (wi == 0) {
                    v0.x = __uint_as_float(f2tf(v0.x * QSCALE));
                    v0.y = __uint_as_float(f2tf(v0.y * QSCALE));
                    v1.x = __uint_as_float(f2tf(v1.x * QSCALE));
                    v1.y = __uint_as_float(f2tf(v1.y * QSCALE));
                } else if (wi < 3) {
                    v0.x = __uint_as_float(f2tf(v0.x));
                    v0.y = __uint_as_float(f2tf(v0.y));
                    v1.x = __uint_as_float(f2tf(v1.x));
                    v1.y = __uint_as_float(f2tf(v1.y));
                } else {
                    float2 b = *(const float2*)(bg + col);
                    v0.x = 1.0f / (1.0f + __expf(-(v0.x + b.x)));
                    v0.y = 1.0f / (1.0f + __expf(-(v0.y + b.y)));
                    v1.x = 1.0f / (1.0f + __expf(-(v1.x + b.x)));
                    v1.y = 1.0f / (1.0f + __expf(-(v1.y + b.y)));
                }
                *(float2*)(out + r0 * CDIM + col) = v0;
                *(float2*)(out + r1 * CDIM + col) = v1;
            }
        }
    }
}

__global__ __launch_bounds__(128) void gemm_out_tc(
    const float* __restrict__ A, const float* __restrict__ bias,
    float* __restrict__ out)
{
    extern __shared__ float sm[];
    float* As = sm;
    float* Bs = sm + 64 * PJ_LD;
    const uint32_t* Au = (const uint32_t*)As;
    const uint32_t* Bu = (const uint32_t*)Bs;

    int tid = threadIdx.x;
    size_t rowbase = (size_t)blockIdx.x * 64;

#pragma unroll
    for (int it = 0; it < 16; it++) {
        int idx = it * 128 + tid;
        int m  = idx >> 5;
        int c4 = (idx & 31) << 2;
        *(float4*)(As + m * PJ_LD + c4) =
            *(const float4*)(A + (rowbase + m) * CDIM + c4);
    }
#pragma unroll
    for (int it = 0; it < 32; it++) {
        int idx = it * 128 + tid;
        int k  = idx >> 5;
        int n4 = (idx & 31) << 2;
        *(float4*)(Bs + k * PJ_LD + n4) =
            *(const float4*)(g_wot + k * 128 + n4);
    }
    __syncthreads();

    int w = tid >> 5, lane = tid & 31;
    int gr = lane >> 2, tg = lane & 3;
    int m0 = (w & 1) * 32;
    int nb = (w >> 1) * 64;

    float acc[2][8][4];
    pj_compute(Au, Bu, m0, nb, gr, tg, acc);

#pragma unroll
    for (int im = 0; im < 2; im++) {
        size_t r0 = rowbase + m0 + im * 16 + gr;
        size_t r1 = r0 + 8;
#pragma unroll
        for (int t = 0; t < 8; t++) {
            int col = nb + t * 8 + tg * 2;
            float2 b = *(const float2*)(bias + col);
            float2 v0 = make_float2(acc[im][t][0] + b.x, acc[im][t][1] + b.y);
            float2 v1 = make_float2(acc[im][t][2] + b.x, acc[im][t][3] + b.y);
            *(float2*)(out + r0 * CDIM + col) = v0;
            *(float2*)(out + r1 * CDIM + col) = v1;
        }
    }
}

// =====================================================================
// Kernel 3: flash attention, shuffle-based PV (no P smem buffer)
//   CTA per (qtile=64, head, i). 256 threads / 8 warps.
//   Warp layout: 4 m-tiles x 2 k-halves. Each warp's PV consumes its
//   own QK fragment (k-slice = its QK n-range) via register shuffles.
//   Cross-half O reduction once at the end through small smem buffer.
// smem (floats):
//   Qs  [64][36]   2304
//   Kt  [32][137]  4384
//   Vs  [128][40]  5120
//   Ms  [384], Pmax[128], Psum[128]
//   Ored[64][34]   2176
// total 14624 floats = 58496 B -> 2 CTAs/SM (regs bound)
// =====================================================================
#define KBS   128
#define KT_LD 137
#define OFF_KT   2304
#define OFF_VS   (OFF_KT + 32*KT_LD)          // 6688
#define OFF_MS   (OFF_VS + KBS*40)            // 11808
#define OFF_PMAX (OFF_MS + 384)               // 12192
#define OFF_PSUM (OFF_PMAX + 128)             // 12320
#define OFF_ORED (OFF_PSUM + 128)             // 12448
#define AT_SMEM_FLOATS (OFF_ORED + 64*34)     // 14624
#define AT_SMEM_BYTES  (AT_SMEM_FLOATS*4)     // 58496

__global__ __launch_bounds__(256, 2) void attn_flash(const float* __restrict__ mask)
{
    extern __shared__ float sm[];
    float* Qs   = sm;
    float* Kt   = sm + OFF_KT;
    float* Vs   = sm + OFF_VS;
    float* Ms   = sm + OFF_MS;
    float* Pmax = sm + OFF_PMAX;
    float* Psum = sm + OFF_PSUM;
    float* Ored = sm + OFF_ORED;
    const uint32_t* Qu = (const uint32_t*)Qs;
    const uint32_t* Ku = (const uint32_t*)Kt;
    const uint32_t* Vu = (const uint32_t*)Vs;

    int tid = threadIdx.x;
    int qt  = blockIdx.x;                 // 0..5
    int h   = blockIdx.y;                 // 0..3
    int i   = blockIdx.z;                 // 0..383
    size_t base = (size_t)i * JDIM;
    int col0 = h * HDIM;
    int qbase = qt * 64;

    // ---- mask bias + Q fill ----
    for (int k = tid; k < 384; k += 256)
        Ms[k] = 1e9f * (mask[base + k] - 1.0f);
    {
        int q  = tid >> 2;
        int d4 = (tid & 3) << 2;
#pragma unroll
        for (int half2 = 0; half2 < 2; half2++) {
            *(float4*)(Qs + q * 36 + d4 + 16*half2) =
                *(const float4*)(g_q + (base + qbase + q) * CDIM + col0 + d4 + 16*half2);
        }
    }
    __syncthreads();

    int w    = tid >> 5;
    int lane = tid & 31;
    int gr   = lane >> 2;   // 0..7
    int tg   = lane & 3;    // 0..3
    int m0   = (w & 3) * 16;
    int half = w >> 2;      // 0..1 (k-half)
    int nh   = half * 64;   // this warp's 64-col slice within k-block

    // hoist Q fragments
    uint32_t aq[4][4];
#pragma unroll
    for (int ks = 0; ks < 4; ks++) {
        int k0 = ks * 8;
        aq[ks][0] = Qu[(m0+gr)   * 36 + k0 + tg];
        aq[ks][1] = Qu[(m0+gr+8) * 36 + k0 + tg];
        aq[ks][2] = Qu[(m0+gr)   * 36 + k0 + tg + 4];
        aq[ks][3] = Qu[(m0+gr+8) * 36 + k0 + tg + 4];
    }

    const float* tb0 = g_tb + (size_t)h * NTOK + (size_t)(qbase + m0 + gr) * JDIM;
    const float* tb1 = tb0 + 8 * JDIM;

    // O accumulator: 4 d-tiles (full d=32) for rows r0, r1
    float oacc[4][4];
#pragma unroll
    for (int t = 0; t < 4; t++)
#pragma unroll
        for (int e = 0; e < 4; e++) oacc[t][e] = 0.0f;
    float mrun0 = -1e30f, mrun1 = -1e30f;
    float l0 = 0.0f, l1 = 0.0f;

    int r0 = m0 + gr, r1 = r0 + 8;
    int srcA = gr * 4 + (tg >> 1);
    int srcB = srcA + 2;
    bool odd = (tg & 1);

#pragma unroll 1
    for (int kb = 0; kb < 3; kb++) {
        __syncthreads();   // previous block's Vs reads complete
        // ---- fill Kt (transposed) and Vs ----
#pragma unroll
        for (int it = 0; it < 4; it++) {
            int idx = it * 256 + tid;
            int k  = idx >> 3;
            int d4 = (idx & 7) << 2;
            size_t grow = (base + kb * KBS + k) * CDIM + col0 + d4;
            float4 kv = *(const float4*)(g_k + grow);
            Kt[(d4+0)*KT_LD + k] = kv.x;
            Kt[(d4+1)*KT_LD + k] = kv.y;
            Kt[(d4+2)*KT_LD + k] = kv.z;
            Kt[(d4+3)*KT_LD + k] = kv.w;
            *(float4*)(Vs + k * 40 + d4) = *(const float4*)(g_v + grow);
        }
        __syncthreads();

        // ---- QK^T -> sacc ----
        float sacc[8][4];
#pragma unroll
        for (int t = 0; t < 8; t++)
#pragma unroll
            for (int e = 0; e < 4; e++) sacc[t][e] = 0.0f;

#pragma unroll
        for (int ks = 0; ks < 4; ks++) {
            int k0 = ks * 8;
#pragma unroll
            for (int t = 0; t < 8; t++) {
                int n0 = nh + t * 8;
                uint32_t b0 = Ku[(k0+tg)   * KT_LD + n0 + gr];
                uint32_t b1 = Ku[(k0+tg+4) * KT_LD + n0 + gr];
                mma_tf32(sacc[t], aq[ks][0], aq[ks][1], aq[ks][2], aq[ks][3], b0, b1);
            }
        }

        // ---- biases + block row max ----
        float mA = -1e30f, mB = -1e30f;
        int kgbase = kb * KBS + nh;
#pragma unroll
        for (int t = 0; t < 8; t++) {
            int col = kgbase + t * 8 + tg * 2;
            float2 tA = *(const float2*)(tb0 + col);
            float2 tB = *(const float2*)(tb1 + col);
            float2 mm = *(const float2*)(Ms + col);
            sacc[t][0] += tA.x + mm.x;  sacc[t][1] += tA.y + mm.y;
            sacc[t][2] += tB.x + mm.x;  sacc[t][3] += tB.y + mm.y;
            mA = fmaxf(mA, fmaxf(sacc[t][0], sacc[t][1]));
            mB = fmaxf(mB, fmaxf(sacc[t][2], sacc[t][3]));
        }
        mA = fmaxf(mA, __shfl_xor_sync(0xffffffffu, mA, 1));
        mA = fmaxf(mA, __shfl_xor_sync(0xffffffffu, mA, 2));
        mB = fmaxf(mB, __shfl_xor_sync(0xffffffffu, mB, 1));
        mB = fmaxf(mB, __shfl_xor_sync(0xffffffffu, mB, 2));
        if (tg == 0) {
            Pmax[r0 * 2 + half] = mA;
            Pmax[r1 * 2 + half] = mB;
        }
        __syncthreads();

        // ---- online max update ----
        float bm0 = fmaxf(Pmax[r0*2], Pmax[r0*2+1]);
        float bm1 = fmaxf(Pmax[r1*2], Pmax[r1*2+1]);
        float mn0 = fmaxf(mrun0, bm0);
        float mn1 = fmaxf(mrun1, bm1);
        float f0 = __expf(mrun0 - mn0);
        float f1 = __expf(mrun1 - mn1);
        mrun0 = mn0; mrun1 = mn1;

        // ---- exp in registers (tf32 bits into sacc), row sums ----
        float s0 = 0.0f, s1 = 0.0f;
#pragma unroll
        for (int t = 0; t < 8; t++) {
            float e0 = __expf(sacc[t][0] - mn0);
            float e1 = __expf(sacc[t][1] - mn0);
            float e2 = __expf(sacc[t][2] - mn1);
            float e3 = __expf(sacc[t][3] - mn1);
            s0 += e0 + e1;
            s1 += e2 + e3;
            sacc[t][0] = __uint_as_float(f2tf(e0));
            sacc[t][1] = __uint_as_float(f2tf(e1));
            sacc[t][2] = __uint_as_float(f2tf(e2));
            sacc[t][3] = __uint_as_float(f2tf(e3));
        }
        s0 += __shfl_xor_sync(0xffffffffu, s0, 1);
        s0 += __shfl_xor_sync(0xffffffffu, s0, 2);
        s1 += __shfl_xor_sync(0xffffffffu, s1, 1);
        s1 += __shfl_xor_sync(0xffffffffu, s1, 2);
        if (tg == 0) {
            Psum[r0 * 2 + half] = s0;
            Psum[r1 * 2 + half] = s1;
        }
        __syncthreads();

        // ---- rescale running state ----
        l0 = l0 * f0 + Psum[r0*2] + Psum[r0*2+1];
        l1 = l1 * f1 + Psum[r1*2] + Psum[r1*2+1];
#pragma unroll
        for (int t = 0; t < 4; t++) {
            oacc[t][0] *= f0;  oacc[t][1] *= f0;
            oacc[t][2] *= f1;  oacc[t][3] *= f1;
        }

        // ---- PV over this warp's k-slice, A-frags via shuffle ----
#pragma unroll
        for (int kk = 0; kk < 8; kk++) {
            float x0 = __shfl_sync(0xffffffffu, sacc[kk][0], srcA);
            float y0 = __shfl_sync(0xffffffffu, sacc[kk][1], srcA);
            float x1 = __shfl_sync(0xffffffffu, sacc[kk][2], srcA);
            float y1 = __shfl_sync(0xffffffffu, sacc[kk][3], srcA);
            float X0 = __shfl_sync(0xffffffffu, sacc[kk][0], srcB);
            float Y0 = __shfl_sync(0xffffffffu, sacc[kk][1], srcB);
            float X1 = __shfl_sync(0xffffffffu, sacc[kk][2], srcB);
            float Y1 = __shfl_sync(0xffffffffu, sacc[kk][3], srcB);
            uint32_t a0 = __float_as_uint(odd ? y0 : x0);  // (r0, tg)
            uint32_t a1 = __float_as_uint(odd ? y1 : x1);  // (r1, tg)
            uint32_t a2 = __float_as_uint(odd ? Y0 : X0);  // (r0, tg+4)
            uint32_t a3 = __float_as_uint(odd ? Y1 : X1);  // (r1, tg+4)
            int k0 = nh + kk * 8;
#pragma unroll
            for (int dt = 0; dt < 4; dt++) {
                int n0 = dt * 8;
                uint32_t b0 = Vu[(k0+tg)   * 40 + n0 + gr];
                uint32_t b1 = Vu[(k0+tg+4) * 40 + n0 + gr];
                mma_tf32(oacc[dt], a0, a1, a2, a3, b0, b1);
            }
        }
    }

    // ---- cross-half O reduction + epilogue ----
    if (half == 1) {
#pragma unroll
        for (int dt = 0; dt < 4; dt++) {
            int c = dt * 8 + tg * 2;
            *(float2*)(Ored + r0 * 34 + c) = make_float2(oacc[dt][0], oacc[dt][1]);
            *(float2*)(Ored + r1 * 34 + c) = make_float2(oacc[dt][2], oacc[dt][3]);
        }
    }
    __syncthreads();
    if (half == 0) {
        float inv0 = 1.0f / l0;
        float inv1 = 1.0f / l1;
        size_t tok0 = base + qbase + r0;
        size_t tok1 = base + qbase + r1;
#pragma unroll
        for (int dt = 0; dt < 4; dt++) {
            int c = dt * 8 + tg * 2;
            float2 h0 = *(const float2*)(Ored + r0 * 34 + c);
            float2 h1 = *(const float2*)(Ored + r1 * 34 + c);
            int col = col0 + c;
            float2 gA = *(const float2*)(g_gt + tok0 * CDIM + col);
            float2 gB = *(const float2*)(g_gt + tok1 * CDIM + col);
            float2 o0, o1;
            o0.x = __uint_as_float(f2tf((oacc[dt][0] + h0.x) * inv0 * gA.x));
            o0.y = __uint_as_float(f2tf((oacc[dt][1] + h0.y) * inv0 * gA.y));
            o1.x = __uint_as_float(f2tf((oacc[dt][2] + h1.x) * inv1 * gB.x));
            o1.y = __uint_as_float(f2tf((oacc[dt][3] + h1.y) * inv1 * gB.y));
            *(float2*)(g_og + tok0 * CDIM + col) = o0;
            *(float2*)(g_og + tok1 * CDIM + col) = o1;
        }
    }
}

// =====================================================================
// launch
// =====================================================================
extern "C" void kernel_launch(void* const* d_in, const int* in_sizes, int n_in,
                              void* d_out, int out_size)
{
    const float* x    = (const float*)d_in[0];
    const float* mask = (const float*)d_in[1];
    const float* lnw  = (const float*)d_in[2];
    const float* lnb  = (const float*)d_in[3];
    const float* wz   = (const float*)d_in[4];
    const float* bz   = (const float*)d_in[5];
    const float* wq   = (const float*)d_in[6];
    const float* wk   = (const float*)d_in[7];
    const float* wv   = (const float*)d_in[8];
    const float* wg   = (const float*)d_in[9];
    const float* bg   = (const float*)d_in[10];
    const float* wo   = (const float*)d_in[11];
    const float* bo   = (const float*)d_in[12];
    float* out = (float*)d_out;

    float *p_xln, *p_og;
    cudaGetSymbolAddress((void**)&p_xln, g_xln);
    cudaGetSymbolAddress((void**)&p_og,  g_og);

    cudaFuncSetAttribute(proj4_tc, cudaFuncAttributeMaxDynamicSharedMemorySize,
                         PJ_SMEM_BYTES);
    cudaFuncSetAttribute(gemm_out_tc, cudaFuncAttributeMaxDynamicSharedMemorySize,
                         PJ_SMEM_BYTES);
    cudaFuncSetAttribute(attn_flash, cudaFuncAttributeMaxDynamicSharedMemorySize,
                         AT_SMEM_BYTES);

    // 0) weight conversion (tf32)
    wconv_kernel<<<320, 256>>>(wq, wk, wv, wg, wo);

    // 1) LayerNorm + tri-bias
    ln_z_kernel<<<NTOK / 8, 256>>>(x, lnw, lnb, wz, bz);

    // 2) fused projections q/k/v/gate (tensor)
    proj4_tc<<<NTOK / 64, 128, PJ_SMEM_BYTES>>>(p_xln, bg);

    // 3) flash attention (shuffle PV), gate fused
    attn_flash<<<dim3(6, HEADS, IDIM), 256, AT_SMEM_BYTES>>>(mask);

    // 4) output projection (tensor)
    gemm_out_tc<<<NTOK / 64, 128, PJ_SMEM_BYTES>>>(p_og, bo, out);
}